// round 6
// baseline (speedup 1.0000x reference)
#include <cuda_runtime.h>

#define BN 4096
#define DN 128
#define MN 8192
#define KS 4
#define QN (2*BN*DN)
#define HALFQ (BN*DN)
#define OFF_LOSS 1048576
#define OFF_IDS  1048577
#define OFF_PERP 1081345

typedef unsigned long long ull;

// ---------- device scratch ----------
__device__ float g_Enorm[KS*MN];
__device__ float g_xnorm0[2*BN];
__device__ float g_xnormR[2*BN];
__device__ float g_res[QN];
__device__ float g_q[QN];
__device__ ull   g_min[2*BN];
__device__ int   g_counts[KS*2*MN];
__device__ int   g_idx[2*BN*KS];
__device__ float g_ph[2ull*BN*MN];
__device__ float g_lg[2ull*BN*MN];
__device__ float g_Sc[(size_t)BN*BN];
__device__ unsigned g_minkey;
__device__ float g_rowlog[BN];
__device__ float g_mse[256*4];

// ---------- helpers ----------
__device__ __forceinline__ unsigned sortkey(float v) {
    unsigned u = __float_as_uint(v);
    return (u & 0x80000000u) ? ~u : (u | 0x80000000u);
}
__device__ __forceinline__ float unsortkey(unsigned k) {
    return (k & 0x80000000u) ? __uint_as_float(k & 0x7FFFFFFFu)
                             : __uint_as_float(~k);
}
__device__ __forceinline__ ull packdi(float v, int idx) {
    return ((ull)sortkey(v) << 32) | (unsigned)idx;
}
__device__ __forceinline__ ull pk2(float x) {
    ull r; asm("mov.b64 %0, {%1, %1};" : "=l"(r) : "f"(x)); return r;
}
__device__ __forceinline__ void fma2(ull &d, ull a, ull b) {
    asm("fma.rn.f32x2 %0, %1, %2, %0;" : "+l"(d) : "l"(a), "l"(b));
}
__device__ __forceinline__ void unpk2(float &lo, float &hi, ull v) {
    asm("mov.b64 {%0, %1}, %2;" : "=f"(lo), "=f"(hi) : "l"(v));
}

// ---------- row norms ----------
__global__ __launch_bounds__(256) void k_rownorm(const float* __restrict__ Xin,
                                                 int nrows, int mode, int off) {
    int w = (blockIdx.x * 256 + threadIdx.x) >> 5;
    int lane = threadIdx.x & 31;
    if (w >= nrows) return;
    const float* X = (mode == 2) ? g_res : Xin;
    float* dst = (mode == 0) ? g_Enorm : ((mode == 1) ? g_xnorm0 : g_xnormR);
    float4 v = reinterpret_cast<const float4*>(X + (size_t)w * DN)[lane];
    float s = v.x*v.x + v.y*v.y + v.z*v.z + v.w*v.w;
    #pragma unroll
    for (int o = 16; o; o >>= 1) s += __shfl_xor_sync(0xFFFFFFFFu, s, o);
    if (lane == 0) dst[off + w] = s;
}

// ---------- init ----------
__global__ __launch_bounds__(256) void k_init(const float* __restrict__ pcf,
                                              const float* __restrict__ plm) {
    int stride = gridDim.x * 256;
    for (int i = blockIdx.x * 256 + threadIdx.x; i < QN; i += stride) {
        g_res[i] = (i < HALFQ) ? pcf[i] : plm[i - HALFQ];
        g_q[i] = 0.0f;
    }
    for (int i = blockIdx.x * 256 + threadIdx.x; i < KS*2*MN; i += stride)
        g_counts[i] = 0;
    if (blockIdx.x == 0 && threadIdx.x == 0) g_minkey = 0xFFFFFFFFu;
}

__global__ __launch_bounds__(256) void k_resetmin() {
    int i = blockIdx.x * 256 + threadIdx.x;
    if (i < 2*BN) g_min[i] = 0xFFFFFFFFFFFFFFFFull;
}

// ---------- argmin distance GEMM (FFMA2), grid (128,64,2) ----------
// smem: resSd (dup u64) 64x65 ull = 33280B ; eT (transposed) 64x68 f = 17408B
__global__ __launch_bounds__(256) void k_argmin(const float* __restrict__ emb, int stage) {
    extern __shared__ __align__(16) char smem_a[];
    ull*   resSd = (ull*)smem_a;
    float* eT    = (float*)(resSd + 64*65);
    const int tid = threadIdx.x;
    const int tx = tid & 15, ty = tid >> 4;
    const int stream = blockIdx.z;
    const int b0 = blockIdx.y * 64;
    const int m0 = blockIdx.x * 64;
    const float* resp = g_res + (size_t)stream * HALFQ;
    const float* Ep = emb + (size_t)stage * MN * DN;
    const float* En = g_Enorm + stage * MN;

    float xn[4];
    #pragma unroll
    for (int i = 0; i < 4; i++) xn[i] = g_xnormR[stream*BN + b0 + 4*ty + i];

    ull acc[4][2];
    #pragma unroll
    for (int i = 0; i < 4; i++) { acc[i][0] = 0ull; acc[i][1] = 0ull; }

    const int lr = tid >> 4, lc = (tid & 15) * 4;
    for (int dc = 0; dc < 2; dc++) {
        #pragma unroll
        for (int h = 0; h < 4; h++) {
            int row = lr + h*16;
            float4 v = *(const float4*)&resp[(size_t)(b0+row)*DN + dc*64 + lc];
            resSd[row*65 + lc + 0] = pk2(v.x);
            resSd[row*65 + lc + 1] = pk2(v.y);
            resSd[row*65 + lc + 2] = pk2(v.z);
            resSd[row*65 + lc + 3] = pk2(v.w);
            float4 e = *(const float4*)&Ep[(size_t)(m0+row)*DN + dc*64 + lc];
            eT[(lc+0)*68 + row] = e.x;
            eT[(lc+1)*68 + row] = e.y;
            eT[(lc+2)*68 + row] = e.z;
            eT[(lc+3)*68 + row] = e.w;
        }
        __syncthreads();
        #pragma unroll
        for (int d = 0; d < 64; d++) {
            ull A[4];
            #pragma unroll
            for (int i = 0; i < 4; i++) A[i] = resSd[(4*ty+i)*65 + d];
            ulonglong2 bv = *(const ulonglong2*)(eT + d*68 + tx*4);
            #pragma unroll
            for (int i = 0; i < 4; i++) {
                fma2(acc[i][0], A[i], bv.x);
                fma2(acc[i][1], A[i], bv.y);
            }
        }
        __syncthreads();
    }
    ull lb[4];
    #pragma unroll
    for (int i = 0; i < 4; i++) {
        float best = 3.4e38f; int bidx = 0;
        #pragma unroll
        for (int jp = 0; jp < 2; jp++) {
            float lo, hi; unpk2(lo, hi, acc[i][jp]);
            int mc = m0 + tx*4 + jp*2;
            float v0 = (En[mc]   + xn[i]) - 2.0f*lo;
            float v1 = (En[mc+1] + xn[i]) - 2.0f*hi;
            if (v0 < best) { best = v0; bidx = mc; }
            if (v1 < best) { best = v1; bidx = mc+1; }
        }
        lb[i] = packdi(best, bidx);
    }
    ull* red = (ull*)eT;
    #pragma unroll
    for (int i = 0; i < 4; i++) red[(4*ty+i)*16 + tx] = lb[i];
    __syncthreads();
    if (tid < 64) {
        ull kk = red[tid*16];
        #pragma unroll
        for (int t = 1; t < 16; t++) { ull c = red[tid*16 + t]; if (c < kk) kk = c; }
        atomicMin(&g_min[(size_t)stream*BN + b0 + tid], kk);
    }
}

// ---------- gather + residual/q update + histogram ----------
__global__ __launch_bounds__(256) void k_update(const float* __restrict__ emb, int stage) {
    int w = (blockIdx.x * 256 + threadIdx.x) >> 5;
    int lane = threadIdx.x & 31;
    if (w >= 2*BN) return;
    int stream = w >> 12; int b = w & (BN - 1);
    int idx = (int)(g_min[w] & 0xFFFFFFFFull);
    float4 e = reinterpret_cast<const float4*>(emb + ((size_t)stage*MN + idx)*DN)[lane];
    float4* qp = reinterpret_cast<float4*>(g_q + (size_t)w*DN);
    float4* rp = reinterpret_cast<float4*>(g_res + (size_t)w*DN);
    float4 q = qp[lane]; q.x += e.x; q.y += e.y; q.z += e.z; q.w += e.w; qp[lane] = q;
    float4 r = rp[lane]; r.x -= e.x; r.y -= e.y; r.z -= e.z; r.w -= e.w; rp[lane] = r;
    if (lane == 0) {
        g_idx[stream*BN*KS + b*KS + stage] = idx;
        atomicAdd(&g_counts[(stage*2 + stream)*MN + idx], 1);
    }
}

// ---------- cmcm scores (FFMA2): -sqrt(max(dist,0)), original inputs vs last E ----------
__global__ __launch_bounds__(256) void k_scores(const float* __restrict__ emb,
                                                const float* __restrict__ pcf,
                                                const float* __restrict__ plm) {
    extern __shared__ __align__(16) char smem_s[];
    ull*   xSd = (ull*)smem_s;
    float* eT  = (float*)(xSd + 64*65);
    const int tid = threadIdx.x;
    const int tx = tid & 15, ty = tid >> 4;
    const int stream = blockIdx.z;
    const int b0 = blockIdx.y * 64;
    const int m0 = blockIdx.x * 64;
    const float* Xp = (stream == 0) ? pcf : plm;
    const float* Ep = emb + (size_t)(KS-1) * MN * DN;
    const float* En = g_Enorm + (KS-1)*MN;

    float xn[4];
    #pragma unroll
    for (int i = 0; i < 4; i++) xn[i] = g_xnorm0[stream*BN + b0 + 4*ty + i];

    ull acc[4][2];
    #pragma unroll
    for (int i = 0; i < 4; i++) { acc[i][0] = 0ull; acc[i][1] = 0ull; }

    const int lr = tid >> 4, lc = (tid & 15) * 4;
    for (int dc = 0; dc < 2; dc++) {
        #pragma unroll
        for (int h = 0; h < 4; h++) {
            int row = lr + h*16;
            float4 v = *(const float4*)&Xp[(size_t)(b0+row)*DN + dc*64 + lc];
            xSd[row*65 + lc + 0] = pk2(v.x);
            xSd[row*65 + lc + 1] = pk2(v.y);
            xSd[row*65 + lc + 2] = pk2(v.z);
            xSd[row*65 + lc + 3] = pk2(v.w);
            float4 e = *(const float4*)&Ep[(size_t)(m0+row)*DN + dc*64 + lc];
            eT[(lc+0)*68 + row] = e.x;
            eT[(lc+1)*68 + row] = e.y;
            eT[(lc+2)*68 + row] = e.z;
            eT[(lc+3)*68 + row] = e.w;
        }
        __syncthreads();
        #pragma unroll
        for (int d = 0; d < 64; d++) {
            ull A[4];
            #pragma unroll
            for (int i = 0; i < 4; i++) A[i] = xSd[(4*ty+i)*65 + d];
            ulonglong2 bv = *(const ulonglong2*)(eT + d*68 + tx*4);
            #pragma unroll
            for (int i = 0; i < 4; i++) {
                fma2(acc[i][0], A[i], bv.x);
                fma2(acc[i][1], A[i], bv.y);
            }
        }
        __syncthreads();
    }
    #pragma unroll
    for (int i = 0; i < 4; i++) {
        size_t rowo = (size_t)stream*BN*MN + (size_t)(b0 + 4*ty + i)*MN;
        #pragma unroll
        for (int jp = 0; jp < 2; jp++) {
            float lo, hi; unpk2(lo, hi, acc[i][jp]);
            int mc = m0 + tx*4 + jp*2;
            float2 o;
            o.x = -sqrtf(fmaxf((En[mc]   + xn[i]) - 2.0f*lo, 0.0f));
            o.y = -sqrtf(fmaxf((En[mc+1] + xn[i]) - 2.0f*hi, 0.0f));
            *(float2*)&g_ph[rowo + mc] = o;
        }
    }
}

// ---------- row softmax + log ----------
__global__ __launch_bounds__(256) void k_softmax() {
    __shared__ __align__(16) float srow[MN];
    __shared__ float red[256];
    int b = blockIdx.x, s = blockIdx.y, tid = threadIdx.x;
    size_t base = (size_t)s*BN*MN + (size_t)b*MN;
    const float4* src = reinterpret_cast<const float4*>(g_ph + base);
    float mx = -3.4e38f;
    #pragma unroll
    for (int k = 0; k < 8; k++) {
        float4 v = src[tid + 256*k];
        reinterpret_cast<float4*>(srow)[tid + 256*k] = v;
        mx = fmaxf(mx, fmaxf(fmaxf(v.x, v.y), fmaxf(v.z, v.w)));
    }
    red[tid] = mx; __syncthreads();
    for (int o = 128; o > 0; o >>= 1) {
        if (tid < o) red[tid] = fmaxf(red[tid], red[tid + o]);
        __syncthreads();
    }
    mx = red[0]; __syncthreads();
    float sum = 0.0f;
    #pragma unroll
    for (int k = 0; k < 8; k++) {
        float4 v = reinterpret_cast<float4*>(srow)[tid + 256*k];
        v.x = expf(v.x - mx); v.y = expf(v.y - mx);
        v.z = expf(v.z - mx); v.w = expf(v.w - mx);
        reinterpret_cast<float4*>(srow)[tid + 256*k] = v;
        sum += v.x + v.y + v.z + v.w;
    }
    red[tid] = sum; __syncthreads();
    for (int o = 128; o > 0; o >>= 1) {
        if (tid < o) red[tid] = red[tid] + red[tid + o];
        __syncthreads();
    }
    sum = red[0];
    float4* dph = reinterpret_cast<float4*>(g_ph + base);
    float4* dlg = reinterpret_cast<float4*>(g_lg + base);
    #pragma unroll
    for (int k = 0; k < 8; k++) {
        float4 v = reinterpret_cast<float4*>(srow)[tid + 256*k];
        v.x /= sum; v.y /= sum; v.z /= sum; v.w /= sum;
        dph[tid + 256*k] = v;
        float4 l;
        l.x = logf(v.x + 1e-10f); l.y = logf(v.y + 1e-10f);
        l.z = logf(v.z + 1e-10f); l.w = logf(v.w + 1e-10f);
        dlg[tid + 256*k] = l;
    }
}

// ---------- Scode GEMM (FFMA2) with fused global min; 1D grid 4096, G=8 swizzle ----------
// smem: sA1,sA2 dup u64 64x33 (16896B each); sB1,sB2 transposed 32x68 f (8704B each)
__global__ __launch_bounds__(256) void k_scode() {
    extern __shared__ __align__(16) char smem_c[];
    ull*   sA1 = (ull*)smem_c;
    ull*   sA2 = sA1 + 64*33;
    float* sB1 = (float*)(sA2 + 64*33);
    float* sB2 = sB1 + 32*68;
    const int tid = threadIdx.x;
    const int tx = tid & 15, ty = tid >> 4;
    int bid = blockIdx.x;
    int group  = bid >> 9;          // /(8*64)
    int within = bid & 511;
    const int i0 = (group*8 + (within & 7)) * 64;
    const int j0 = (within >> 3) * 64;
    const float* Ppcf = g_ph;
    const float* Pplm = g_ph + (size_t)BN*MN;
    const float* Lpcf = g_lg;
    const float* Lplm = g_lg + (size_t)BN*MN;

    ull acc[4][2];
    #pragma unroll
    for (int i = 0; i < 4; i++) { acc[i][0] = 0ull; acc[i][1] = 0ull; }

    const int lr = tid >> 3, lc = (tid & 7) * 4;
    for (int k0 = 0; k0 < MN; k0 += 32) {
        #pragma unroll
        for (int h = 0; h < 2; h++) {
            int row = lr + h*32;
            float4 v;
            v = *(const float4*)&Ppcf[(size_t)(i0+row)*MN + k0 + lc];
            sA1[row*33+lc+0] = pk2(v.x); sA1[row*33+lc+1] = pk2(v.y);
            sA1[row*33+lc+2] = pk2(v.z); sA1[row*33+lc+3] = pk2(v.w);
            v = *(const float4*)&Pplm[(size_t)(i0+row)*MN + k0 + lc];
            sA2[row*33+lc+0] = pk2(v.x); sA2[row*33+lc+1] = pk2(v.y);
            sA2[row*33+lc+2] = pk2(v.z); sA2[row*33+lc+3] = pk2(v.w);
            v = *(const float4*)&Lplm[(size_t)(j0+row)*MN + k0 + lc];
            sB1[(lc+0)*68+row] = v.x; sB1[(lc+1)*68+row] = v.y;
            sB1[(lc+2)*68+row] = v.z; sB1[(lc+3)*68+row] = v.w;
            v = *(const float4*)&Lpcf[(size_t)(j0+row)*MN + k0 + lc];
            sB2[(lc+0)*68+row] = v.x; sB2[(lc+1)*68+row] = v.y;
            sB2[(lc+2)*68+row] = v.z; sB2[(lc+3)*68+row] = v.w;
        }
        __syncthreads();
        #pragma unroll
        for (int kk = 0; kk < 32; kk++) {
            ull A1[4], A2[4];
            #pragma unroll
            for (int i = 0; i < 4; i++) {
                A1[i] = sA1[(4*ty+i)*33 + kk];
                A2[i] = sA2[(4*ty+i)*33 + kk];
            }
            ulonglong2 b1 = *(const ulonglong2*)(sB1 + kk*68 + tx*4);
            ulonglong2 b2 = *(const ulonglong2*)(sB2 + kk*68 + tx*4);
            #pragma unroll
            for (int i = 0; i < 4; i++) {
                fma2(acc[i][0], A1[i], b1.x);
                fma2(acc[i][0], A2[i], b2.x);
                fma2(acc[i][1], A1[i], b1.y);
                fma2(acc[i][1], A2[i], b2.y);
            }
        }
        __syncthreads();
    }
    float lmin = 3.4e38f;
    #pragma unroll
    for (int i = 0; i < 4; i++) {
        size_t rowo = (size_t)(i0 + 4*ty + i)*BN + j0;
        #pragma unroll
        for (int jp = 0; jp < 2; jp++) {
            float lo, hi; unpk2(lo, hi, acc[i][jp]);
            *(float2*)&g_Sc[rowo + tx*4 + jp*2] = make_float2(lo, hi);
            lmin = fminf(lmin, fminf(lo, hi));
        }
    }
    float* red = sB1;   // reuse (all smem reads done, post-sync)
    red[tid] = lmin; __syncthreads();
    for (int o = 128; o > 0; o >>= 1) {
        if (tid < o) red[tid] = fminf(red[tid], red[tid + o]);
        __syncthreads();
    }
    if (tid == 0) atomicMin(&g_minkey, sortkey(red[0]));
}

// ---------- per-row: log(diag(E)/(rowsum(E)+eps)) ----------
__global__ __launch_bounds__(256) void k_rowratio() {
    __shared__ float red[256];
    int i = blockIdx.x, tid = threadIdx.x;
    float Mx = -unsortkey(g_minkey);
    const float* row = g_Sc + (size_t)i * BN;
    float sum = 0.0f;
    #pragma unroll
    for (int k = 0; k < 16; k++) sum += expf(row[tid + 256*k] + Mx);
    red[tid] = sum; __syncthreads();
    for (int o = 128; o > 0; o >>= 1) {
        if (tid < o) red[tid] = red[tid] + red[tid + o];
        __syncthreads();
    }
    if (tid == 0) {
        float ratio = expf(row[i] + Mx) / (red[0] + 1e-5f);
        g_rowlog[i] = logf(ratio);
    }
}

// ---------- quantized = fl(x + fl(q - x)) ----------
__global__ __launch_bounds__(256) void k_quant(const float* __restrict__ pcf,
                                               const float* __restrict__ plm,
                                               float* __restrict__ out) {
    int e = blockIdx.x * 256 + threadIdx.x;
    if (e >= QN) return;
    float x = (e < HALFQ) ? pcf[e] : plm[e - HALFQ];
    float t = g_q[e] - x;
    out[e] = x + t;
}

__global__ __launch_bounds__(256) void k_ids(float* __restrict__ out) {
    int e = blockIdx.x * 256 + threadIdx.x;
    if (e < 2*BN*KS) out[OFF_IDS + e] = (float)g_idx[e];
}

__global__ __launch_bounds__(256) void k_mse(const float* __restrict__ pcf,
                                             const float* __restrict__ plm,
                                             const float* __restrict__ out) {
    __shared__ float red[256];
    int tid = threadIdx.x, bid = blockIdx.x;
    float s[4] = {0.f, 0.f, 0.f, 0.f};
    #pragma unroll
    for (int k = 0; k < 8; k++) {
        int e = bid*2048 + k*256 + tid;
        float qp = out[e], qm = out[HALFQ + e];
        float xp = pcf[e], xm = plm[e];
        float d;
        d = xp - qp; s[0] += d*d;
        d = xp - qm; s[1] += d*d;
        d = xm - qm; s[2] += d*d;
        d = xm - qp; s[3] += d*d;
    }
    #pragma unroll
    for (int c = 0; c < 4; c++) {
        red[tid] = s[c]; __syncthreads();
        for (int o = 128; o > 0; o >>= 1) {
            if (tid < o) red[tid] = red[tid] + red[tid + o];
            __syncthreads();
        }
        if (tid == 0) g_mse[bid*4 + c] = red[0];
        __syncthreads();
    }
}

__global__ __launch_bounds__(256) void k_perp(float* __restrict__ out) {
    __shared__ float red[256];
    int b = blockIdx.x, tid = threadIdx.x;
    int k = b >> 1, s = b & 1;
    const int* cnt = g_counts + (k*2 + s)*MN;
    float sum = 0.0f;
    #pragma unroll
    for (int t = 0; t < 32; t++) {
        float avg = (float)cnt[tid + 256*t] / (float)BN;
        sum += avg * logf(avg + 1e-10f);
    }
    red[tid] = sum; __syncthreads();
    for (int o = 128; o > 0; o >>= 1) {
        if (tid < o) red[tid] = red[tid] + red[tid + o];
        __syncthreads();
    }
    if (tid == 0) out[OFF_PERP + k*2 + s] = expf(-red[0]);
}

__global__ __launch_bounds__(256) void k_final(float* __restrict__ out) {
    __shared__ float red[256];
    int tid = threadIdx.x;
    float s = 0.0f;
    #pragma unroll
    for (int k = 0; k < 16; k++) s += g_rowlog[tid + 256*k];
    red[tid] = s; __syncthreads();
    for (int o = 128; o > 0; o >>= 1) {
        if (tid < o) red[tid] = red[tid] + red[tid + o];
        __syncthreads();
    }
    float Lc = -(red[0] / (float)BN);
    __syncthreads();
    float m[4];
    for (int c = 0; c < 4; c++) {
        red[tid] = g_mse[tid*4 + c]; __syncthreads();
        for (int o = 128; o > 0; o >>= 1) {
            if (tid < o) red[tid] = red[tid] + red[tid + o];
            __syncthreads();
        }
        m[c] = red[0] / (float)HALFQ;
        __syncthreads();
    }
    if (tid == 0) {
        float pcf_loss = 0.5f*m[0] + 0.25f*m[1];
        float plm_loss = 0.5f*m[2] + 0.25f*m[3];
        out[OFF_LOSS] = 0.5f*Lc + pcf_loss + plm_loss;
    }
}

// ---------- orchestration ----------
extern "C" void kernel_launch(void* const* d_in, const int* in_sizes, int n_in,
                              void* d_out, int out_size) {
    const float* pcf = (const float*)d_in[0];
    const float* plm = (const float*)d_in[1];
    const float* emb = (const float*)d_in[2];
    float* out = (float*)d_out;

    const int SM_ARG = 64*65*8 + 64*68*4;           // 50688
    const int SM_SC  = 2*64*33*8 + 2*32*68*4;       // 51200
    cudaFuncSetAttribute(k_argmin, cudaFuncAttributeMaxDynamicSharedMemorySize, SM_ARG);
    cudaFuncSetAttribute(k_scores, cudaFuncAttributeMaxDynamicSharedMemorySize, SM_ARG);
    cudaFuncSetAttribute(k_scode,  cudaFuncAttributeMaxDynamicSharedMemorySize, SM_SC);

    k_init<<<256, 256>>>(pcf, plm);
    k_rownorm<<<4096, 256>>>(emb, KS*MN, 0, 0);
    k_rownorm<<<512, 256>>>(pcf, BN, 1, 0);
    k_rownorm<<<512, 256>>>(plm, BN, 1, BN);

    for (int s = 0; s < KS; s++) {
        k_resetmin<<<32, 256>>>();
        k_rownorm<<<1024, 256>>>(nullptr, 2*BN, 2, 0);
        k_argmin<<<dim3(128, 64, 2), 256, SM_ARG>>>(emb, s);
        k_update<<<1024, 256>>>(emb, s);
    }

    k_scores<<<dim3(128, 64, 2), 256, SM_ARG>>>(emb, pcf, plm);
    k_softmax<<<dim3(BN, 2), 256>>>();
    k_scode<<<4096, 256, SM_SC>>>();
    k_rowratio<<<BN, 256>>>();

    k_quant<<<QN/256, 256>>>(pcf, plm, out);
    k_ids<<<(2*BN*KS)/256, 256>>>(out);
    k_mse<<<256, 256>>>(pcf, plm, out);
    k_perp<<<8, 256>>>(out);
    k_final<<<1, 256>>>(out);
}

// round 8
// speedup vs baseline: 2.5287x; 2.5287x over previous
#include <cuda_runtime.h>
#include <cstdint>

#define BN 4096
#define DN 128
#define MN 8192
#define KS 4
#define QN (2*BN*DN)
#define HALFQ (BN*DN)
#define OFF_LOSS 1048576
#define OFF_IDS  1048577
#define OFF_PERP 1081345

typedef unsigned long long ull;

// ---------- device scratch ----------
__device__ float g_Enorm[KS*MN];
__device__ float g_xnorm0[2*BN];
__device__ float g_xnormR[2*BN];
__device__ float g_res[QN];
__device__ float g_q[QN];
__device__ ull   g_min[2*BN];
__device__ int   g_counts[KS*2*MN];
__device__ int   g_idx[2*BN*KS];
__device__ float g_ph[2ull*BN*MN];
__device__ float g_lg[2ull*BN*MN];
__device__ float g_Sc[(size_t)BN*BN];
__device__ unsigned g_minkey;
__device__ float g_rowlog[BN];
__device__ float g_mse[256*4];

// ---------- helpers ----------
__device__ __forceinline__ unsigned sortkey(float v) {
    unsigned u = __float_as_uint(v);
    return (u & 0x80000000u) ? ~u : (u | 0x80000000u);
}
__device__ __forceinline__ float unsortkey(unsigned k) {
    return (k & 0x80000000u) ? __uint_as_float(k & 0x7FFFFFFFu)
                             : __uint_as_float(~k);
}
__device__ __forceinline__ ull packdi(float v, int idx) {
    return ((ull)sortkey(v) << 32) | (unsigned)idx;
}
__device__ __forceinline__ float tf32r(float x) {
    float r;
    asm("{\n\t.reg .b32 t;\n\tcvt.rna.tf32.f32 t, %1;\n\tmov.b32 %0, t;\n\t}"
        : "=f"(r) : "f"(x));
    return r;
}
__device__ __forceinline__ void mma_tf32(float* c, const uint4& a,
                                         uint32_t b0, uint32_t b1) {
    asm volatile("mma.sync.aligned.m16n8k8.row.col.f32.tf32.tf32.f32 "
        "{%0,%1,%2,%3}, {%4,%5,%6,%7}, {%8,%9}, {%0,%1,%2,%3};"
        : "+f"(c[0]), "+f"(c[1]), "+f"(c[2]), "+f"(c[3])
        : "r"(a.x), "r"(a.y), "r"(a.z), "r"(a.w), "r"(b0), "r"(b1));
}

// ---------- row norms ----------
__global__ __launch_bounds__(256) void k_rownorm(const float* __restrict__ Xin,
                                                 int nrows, int mode, int off) {
    int w = (blockIdx.x * 256 + threadIdx.x) >> 5;
    int lane = threadIdx.x & 31;
    if (w >= nrows) return;
    const float* X = (mode == 2) ? g_res : Xin;
    float* dst = (mode == 0) ? g_Enorm : ((mode == 1) ? g_xnorm0 : g_xnormR);
    float4 v = reinterpret_cast<const float4*>(X + (size_t)w * DN)[lane];
    float s = v.x*v.x + v.y*v.y + v.z*v.z + v.w*v.w;
    #pragma unroll
    for (int o = 16; o; o >>= 1) s += __shfl_xor_sync(0xFFFFFFFFu, s, o);
    if (lane == 0) dst[off + w] = s;
}

// ---------- init ----------
__global__ __launch_bounds__(256) void k_init(const float* __restrict__ pcf,
                                              const float* __restrict__ plm) {
    int stride = gridDim.x * 256;
    for (int i = blockIdx.x * 256 + threadIdx.x; i < QN; i += stride) {
        g_res[i] = (i < HALFQ) ? pcf[i] : plm[i - HALFQ];
        g_q[i] = 0.0f;
    }
    for (int i = blockIdx.x * 256 + threadIdx.x; i < KS*2*MN; i += stride)
        g_counts[i] = 0;
    if (blockIdx.x == 0 && threadIdx.x == 0) g_minkey = 0xFFFFFFFFu;
}

__global__ __launch_bounds__(256) void k_resetmin() {
    int i = blockIdx.x * 256 + threadIdx.x;
    if (i < 2*BN) g_min[i] = 0xFFFFFFFFFFFFFFFFull;
}

// ---------- argmin distance GEMM (exact fp32, R5-proven) ----------
__global__ __launch_bounds__(256) void k_argmin(const float* __restrict__ emb, int stage) {
    __shared__ __align__(16) float resS[64*65];
    __shared__ __align__(16) float eS[64*65];
    const int tid = threadIdx.x;
    const int tx = tid & 15, ty = tid >> 4;
    const int stream = blockIdx.z;
    const int b0 = blockIdx.y * 64;
    const int m0 = blockIdx.x * 64;
    const float* resp = g_res + (size_t)stream * HALFQ;
    const float* Ep = emb + (size_t)stage * MN * DN;
    const float* En = g_Enorm + stage * MN;

    float xn[4];
    #pragma unroll
    for (int i = 0; i < 4; i++) xn[i] = g_xnormR[stream*BN + b0 + 4*ty + i];

    float acc[4][4];
    #pragma unroll
    for (int i = 0; i < 4; i++)
        #pragma unroll
        for (int j = 0; j < 4; j++) acc[i][j] = 0.0f;

    for (int dc = 0; dc < 2; dc++) {
        #pragma unroll
        for (int k = 0; k < 16; k++) {
            int e = tid + 256*k; int r = e >> 6; int dd = e & 63;
            resS[r*65 + dd] = resp[(size_t)(b0 + r)*DN + dc*64 + dd];
            eS[r*65 + dd]   = Ep[(size_t)(m0 + r)*DN + dc*64 + dd];
        }
        __syncthreads();
        #pragma unroll
        for (int d = 0; d < 64; d++) {
            float a[4], bb[4];
            #pragma unroll
            for (int i = 0; i < 4; i++) a[i] = resS[(4*ty+i)*65 + d];
            #pragma unroll
            for (int j = 0; j < 4; j++) bb[j] = eS[(tx+16*j)*65 + d];
            #pragma unroll
            for (int i = 0; i < 4; i++)
                #pragma unroll
                for (int j = 0; j < 4; j++) acc[i][j] += a[i]*bb[j];
        }
        __syncthreads();
    }
    ull lb[4];
    #pragma unroll
    for (int i = 0; i < 4; i++) {
        float best = 3.4e38f; int bidx = 0;
        #pragma unroll
        for (int j = 0; j < 4; j++) {
            int mcol = m0 + tx + 16*j;
            float val = (En[mcol] + xn[i]) - 2.0f*acc[i][j];
            if (val < best) { best = val; bidx = mcol; }
        }
        lb[i] = packdi(best, bidx);
    }
    ull* red = (ull*)eS;
    #pragma unroll
    for (int i = 0; i < 4; i++) red[(4*ty+i)*16 + tx] = lb[i];
    __syncthreads();
    if (tid < 64) {
        ull kk = red[tid*16];
        #pragma unroll
        for (int t = 1; t < 16; t++) { ull c = red[tid*16 + t]; if (c < kk) kk = c; }
        atomicMin(&g_min[(size_t)stream*BN + b0 + tid], kk);
    }
}

// ---------- gather + residual/q update + histogram ----------
__global__ __launch_bounds__(256) void k_update(const float* __restrict__ emb, int stage) {
    int w = (blockIdx.x * 256 + threadIdx.x) >> 5;
    int lane = threadIdx.x & 31;
    if (w >= 2*BN) return;
    int stream = w >> 12; int b = w & (BN - 1);
    int idx = (int)(g_min[w] & 0xFFFFFFFFull);
    float4 e = reinterpret_cast<const float4*>(emb + ((size_t)stage*MN + idx)*DN)[lane];
    float4* qp = reinterpret_cast<float4*>(g_q + (size_t)w*DN);
    float4* rp = reinterpret_cast<float4*>(g_res + (size_t)w*DN);
    float4 q = qp[lane]; q.x += e.x; q.y += e.y; q.z += e.z; q.w += e.w; qp[lane] = q;
    float4 r = rp[lane]; r.x -= e.x; r.y -= e.y; r.z -= e.z; r.w -= e.w; rp[lane] = r;
    if (lane == 0) {
        g_idx[stream*BN*KS + b*KS + stage] = idx;
        atomicAdd(&g_counts[(stage*2 + stream)*MN + idx], 1);
    }
}

// ---------- cmcm scores (fp32, R5-proven) ----------
__global__ __launch_bounds__(256) void k_scores(const float* __restrict__ emb,
                                                const float* __restrict__ pcf,
                                                const float* __restrict__ plm) {
    __shared__ __align__(16) float xS[64*65];
    __shared__ __align__(16) float eS[64*65];
    const int tid = threadIdx.x;
    const int tx = tid & 15, ty = tid >> 4;
    const int stream = blockIdx.z;
    const int b0 = blockIdx.y * 64;
    const int m0 = blockIdx.x * 64;
    const float* Xp = (stream == 0) ? pcf : plm;
    const float* Ep = emb + (size_t)(KS-1) * MN * DN;
    const float* En = g_Enorm + (KS-1)*MN;

    float xn[4];
    #pragma unroll
    for (int i = 0; i < 4; i++) xn[i] = g_xnorm0[stream*BN + b0 + 4*ty + i];

    float acc[4][4];
    #pragma unroll
    for (int i = 0; i < 4; i++)
        #pragma unroll
        for (int j = 0; j < 4; j++) acc[i][j] = 0.0f;

    for (int dc = 0; dc < 2; dc++) {
        #pragma unroll
        for (int k = 0; k < 16; k++) {
            int e = tid + 256*k; int r = e >> 6; int dd = e & 63;
            xS[r*65 + dd] = Xp[(size_t)(b0 + r)*DN + dc*64 + dd];
            eS[r*65 + dd] = Ep[(size_t)(m0 + r)*DN + dc*64 + dd];
        }
        __syncthreads();
        #pragma unroll
        for (int d = 0; d < 64; d++) {
            float a[4], bb[4];
            #pragma unroll
            for (int i = 0; i < 4; i++) a[i] = xS[(4*ty+i)*65 + d];
            #pragma unroll
            for (int j = 0; j < 4; j++) bb[j] = eS[(tx+16*j)*65 + d];
            #pragma unroll
            for (int i = 0; i < 4; i++)
                #pragma unroll
                for (int j = 0; j < 4; j++) acc[i][j] += a[i]*bb[j];
        }
        __syncthreads();
    }
    #pragma unroll
    for (int j = 0; j < 4; j++) {
        int mcol = m0 + tx + 16*j;
        float en = En[mcol];
        #pragma unroll
        for (int i = 0; i < 4; i++) {
            float val = fmaxf((en + xn[i]) - 2.0f*acc[i][j], 0.0f);
            g_ph[(size_t)stream*BN*MN + (size_t)(b0 + 4*ty + i)*MN + mcol] = -sqrtf(val);
        }
    }
}

// ---------- row softmax + log ----------
__global__ __launch_bounds__(256) void k_softmax() {
    __shared__ __align__(16) float srow[MN];
    __shared__ float red[256];
    int b = blockIdx.x, s = blockIdx.y, tid = threadIdx.x;
    size_t base = (size_t)s*BN*MN + (size_t)b*MN;
    const float4* src = reinterpret_cast<const float4*>(g_ph + base);
    float mx = -3.4e38f;
    #pragma unroll
    for (int k = 0; k < 8; k++) {
        float4 v = src[tid + 256*k];
        reinterpret_cast<float4*>(srow)[tid + 256*k] = v;
        mx = fmaxf(mx, fmaxf(fmaxf(v.x, v.y), fmaxf(v.z, v.w)));
    }
    red[tid] = mx; __syncthreads();
    for (int o = 128; o > 0; o >>= 1) {
        if (tid < o) red[tid] = fmaxf(red[tid], red[tid + o]);
        __syncthreads();
    }
    mx = red[0]; __syncthreads();
    float sum = 0.0f;
    #pragma unroll
    for (int k = 0; k < 8; k++) {
        float4 v = reinterpret_cast<float4*>(srow)[tid + 256*k];
        v.x = expf(v.x - mx); v.y = expf(v.y - mx);
        v.z = expf(v.z - mx); v.w = expf(v.w - mx);
        reinterpret_cast<float4*>(srow)[tid + 256*k] = v;
        sum += v.x + v.y + v.z + v.w;
    }
    red[tid] = sum; __syncthreads();
    for (int o = 128; o > 0; o >>= 1) {
        if (tid < o) red[tid] = red[tid] + red[tid + o];
        __syncthreads();
    }
    sum = red[0];
    float4* dph = reinterpret_cast<float4*>(g_ph + base);
    float4* dlg = reinterpret_cast<float4*>(g_lg + base);
    #pragma unroll
    for (int k = 0; k < 8; k++) {
        float4 v = reinterpret_cast<float4*>(srow)[tid + 256*k];
        v.x /= sum; v.y /= sum; v.z /= sum; v.w /= sum;
        dph[tid + 256*k] = v;
        float4 l;
        l.x = logf(v.x + 1e-10f); l.y = logf(v.y + 1e-10f);
        l.z = logf(v.z + 1e-10f); l.w = logf(v.w + 1e-10f);
        dlg[tid + 256*k] = l;
    }
}

// ---------- Scode via mma.sync tf32 (portable HMMA path) ----------
// CTA: 128x128 C-tile; 8 warps as 4(M) x 2(N); warp tile 32x64.
// smem (dynamic, 64KB): A1,A2,B1,B2 each 128x32 fp32, stored PRE-PERMUTED into
// m16n8k8 fragment layout so compute fetches are single LDS.128.
__global__ __launch_bounds__(256) void k_scode_mma() {
    extern __shared__ __align__(16) float sm[];
    float* A1 = sm;
    float* A2 = sm + 4096;
    float* B1 = sm + 8192;
    float* B2 = sm + 12288;
    const int tid = threadIdx.x;
    const int lane = tid & 31, wid = tid >> 5;
    const int wy = wid & 3, wx = wid >> 2;
    const int i0 = (blockIdx.x & 31) * 128;
    const int j0 = (blockIdx.x >> 5) * 128;
    const float* Ppcf = g_ph;
    const float* Pplm = g_ph + (size_t)BN*MN;
    const float* Lpcf = g_lg;
    const float* Lplm = g_lg + (size_t)BN*MN;

    float acc[2][8][4];
    #pragma unroll
    for (int mi = 0; mi < 2; mi++)
        #pragma unroll
        for (int nt = 0; nt < 8; nt++)
            #pragma unroll
            for (int c = 0; c < 4; c++) acc[mi][nt][c] = 0.0f;

    for (int kc = 0; kc < 256; kc++) {
        const int kb = kc * 32;
        // ---- stage: gmem float4 -> fragment-permuted smem (tf32-rounded) ----
        #pragma unroll
        for (int t = tid; t < 1024; t += 256) {
            int row = t >> 3, kk4 = (t & 7) * 4;
            int k8 = kk4 >> 3, ch = (kk4 >> 2) & 1;
            // A layout: [(k8*8+mtile)*32 + g*4 + u]*4 + (ch*2 + hi)
            int mtile = row >> 4, r16 = row & 15;
            int baseA = ((k8*8 + mtile)*32 + (r16 & 7)*4)*4 + ch*2 + (r16 >> 3);
            // B layout: [(k8*8+npair)*32 + n*4 + u]*4 + (nhalf*2 + ch)
            int baseB = ((k8*8 + (row >> 4))*32 + (row & 7)*4)*4 + ((row >> 3) & 1)*2 + ch;
            float4 v1 = *(const float4*)&Ppcf[(size_t)(i0+row)*MN + kb + kk4];
            float4 v2 = *(const float4*)&Pplm[(size_t)(i0+row)*MN + kb + kk4];
            float4 w1 = *(const float4*)&Lplm[(size_t)(j0+row)*MN + kb + kk4];
            float4 w2 = *(const float4*)&Lpcf[(size_t)(j0+row)*MN + kb + kk4];
            A1[baseA+0] = tf32r(v1.x); A1[baseA+4] = tf32r(v1.y);
            A1[baseA+8] = tf32r(v1.z); A1[baseA+12] = tf32r(v1.w);
            A2[baseA+0] = tf32r(v2.x); A2[baseA+4] = tf32r(v2.y);
            A2[baseA+8] = tf32r(v2.z); A2[baseA+12] = tf32r(v2.w);
            B1[baseB+0] = tf32r(w1.x); B1[baseB+4] = tf32r(w1.y);
            B1[baseB+8] = tf32r(w1.z); B1[baseB+12] = tf32r(w1.w);
            B2[baseB+0] = tf32r(w2.x); B2[baseB+4] = tf32r(w2.y);
            B2[baseB+8] = tf32r(w2.z); B2[baseB+12] = tf32r(w2.w);
        }
        __syncthreads();
        // ---- compute: 4 k8-steps ----
        #pragma unroll
        for (int s = 0; s < 4; s++) {
            uint4 a1[2], a2[2];
            #pragma unroll
            for (int mi = 0; mi < 2; mi++) {
                a1[mi] = *(const uint4*)&A1[((s*8 + wy*2 + mi)*32 + lane)*4];
                a2[mi] = *(const uint4*)&A2[((s*8 + wy*2 + mi)*32 + lane)*4];
            }
            #pragma unroll
            for (int pp = 0; pp < 4; pp++) {
                uint4 b1 = *(const uint4*)&B1[((s*8 + wx*4 + pp)*32 + lane)*4];
                uint4 b2 = *(const uint4*)&B2[((s*8 + wx*4 + pp)*32 + lane)*4];
                #pragma unroll
                for (int mi = 0; mi < 2; mi++) {
                    mma_tf32(acc[mi][2*pp+0], a1[mi], b1.x, b1.y);
                    mma_tf32(acc[mi][2*pp+1], a1[mi], b1.z, b1.w);
                    mma_tf32(acc[mi][2*pp+0], a2[mi], b2.x, b2.y);
                    mma_tf32(acc[mi][2*pp+1], a2[mi], b2.z, b2.w);
                }
            }
        }
        __syncthreads();
    }
    // ---- epilogue: store + fused global min ----
    float lmin = 3.4e38f;
    #pragma unroll
    for (int mi = 0; mi < 2; mi++) {
        int row = i0 + (wy*2 + mi)*16 + (lane >> 2);
        #pragma unroll
        for (int nt = 0; nt < 8; nt++) {
            int col = j0 + (wx*8 + nt)*8 + (lane & 3)*2;
            float* c = acc[mi][nt];
            *(float2*)&g_Sc[(size_t)row*BN + col]     = make_float2(c[0], c[1]);
            *(float2*)&g_Sc[(size_t)(row+8)*BN + col] = make_float2(c[2], c[3]);
            lmin = fminf(lmin, fminf(fminf(c[0], c[1]), fminf(c[2], c[3])));
        }
    }
    float* red = sm;
    red[tid] = lmin; __syncthreads();
    for (int o = 128; o > 0; o >>= 1) {
        if (tid < o) red[tid] = fminf(red[tid], red[tid + o]);
        __syncthreads();
    }
    if (tid == 0) atomicMin(&g_minkey, sortkey(red[0]));
}

// ---------- per-row: log(diag(E)/(rowsum(E)+eps)) ----------
__global__ __launch_bounds__(256) void k_rowratio() {
    __shared__ float red[256];
    int i = blockIdx.x, tid = threadIdx.x;
    float Mx = -unsortkey(g_minkey);
    const float* row = g_Sc + (size_t)i * BN;
    float sum = 0.0f;
    #pragma unroll
    for (int k = 0; k < 16; k++) sum += expf(row[tid + 256*k] + Mx);
    red[tid] = sum; __syncthreads();
    for (int o = 128; o > 0; o >>= 1) {
        if (tid < o) red[tid] = red[tid] + red[tid + o];
        __syncthreads();
    }
    if (tid == 0) {
        float ratio = expf(row[i] + Mx) / (red[0] + 1e-5f);
        g_rowlog[i] = logf(ratio);
    }
}

// ---------- quantized = fl(x + fl(q - x)) ----------
__global__ __launch_bounds__(256) void k_quant(const float* __restrict__ pcf,
                                               const float* __restrict__ plm,
                                               float* __restrict__ out) {
    int e = blockIdx.x * 256 + threadIdx.x;
    if (e >= QN) return;
    float x = (e < HALFQ) ? pcf[e] : plm[e - HALFQ];
    float t = g_q[e] - x;
    out[e] = x + t;
}

__global__ __launch_bounds__(256) void k_ids(float* __restrict__ out) {
    int e = blockIdx.x * 256 + threadIdx.x;
    if (e < 2*BN*KS) out[OFF_IDS + e] = (float)g_idx[e];
}

__global__ __launch_bounds__(256) void k_mse(const float* __restrict__ pcf,
                                             const float* __restrict__ plm,
                                             const float* __restrict__ out) {
    __shared__ float red[256];
    int tid = threadIdx.x, bid = blockIdx.x;
    float s[4] = {0.f, 0.f, 0.f, 0.f};
    #pragma unroll
    for (int k = 0; k < 8; k++) {
        int e = bid*2048 + k*256 + tid;
        float qp = out[e], qm = out[HALFQ + e];
        float xp = pcf[e], xm = plm[e];
        float d;
        d = xp - qp; s[0] += d*d;
        d = xp - qm; s[1] += d*d;
        d = xm - qm; s[2] += d*d;
        d = xm - qp; s[3] += d*d;
    }
    #pragma unroll
    for (int c = 0; c < 4; c++) {
        red[tid] = s[c]; __syncthreads();
        for (int o = 128; o > 0; o >>= 1) {
            if (tid < o) red[tid] = red[tid] + red[tid + o];
            __syncthreads();
        }
        if (tid == 0) g_mse[bid*4 + c] = red[0];
        __syncthreads();
    }
}

__global__ __launch_bounds__(256) void k_perp(float* __restrict__ out) {
    __shared__ float red[256];
    int b = blockIdx.x, tid = threadIdx.x;
    int k = b >> 1, s = b & 1;
    const int* cnt = g_counts + (k*2 + s)*MN;
    float sum = 0.0f;
    #pragma unroll
    for (int t = 0; t < 32; t++) {
        float avg = (float)cnt[tid + 256*t] / (float)BN;
        sum += avg * logf(avg + 1e-10f);
    }
    red[tid] = sum; __syncthreads();
    for (int o = 128; o > 0; o >>= 1) {
        if (tid < o) red[tid] = red[tid] + red[tid + o];
        __syncthreads();
    }
    if (tid == 0) out[OFF_PERP + k*2 + s] = expf(-red[0]);
}

__global__ __launch_bounds__(256) void k_final(float* __restrict__ out) {
    __shared__ float red[256];
    int tid = threadIdx.x;
    float s = 0.0f;
    #pragma unroll
    for (int k = 0; k < 16; k++) s += g_rowlog[tid + 256*k];
    red[tid] = s; __syncthreads();
    for (int o = 128; o > 0; o >>= 1) {
        if (tid < o) red[tid] = red[tid] + red[tid + o];
        __syncthreads();
    }
    float Lc = -(red[0] / (float)BN);
    __syncthreads();
    float m[4];
    for (int c = 0; c < 4; c++) {
        red[tid] = g_mse[tid*4 + c]; __syncthreads();
        for (int o = 128; o > 0; o >>= 1) {
            if (tid < o) red[tid] = red[tid] + red[tid + o];
            __syncthreads();
        }
        m[c] = red[0] / (float)HALFQ;
        __syncthreads();
    }
    if (tid == 0) {
        float pcf_loss = 0.5f*m[0] + 0.25f*m[1];
        float plm_loss = 0.5f*m[2] + 0.25f*m[3];
        out[OFF_LOSS] = 0.5f*Lc + pcf_loss + plm_loss;
    }
}

// ---------- orchestration ----------
extern "C" void kernel_launch(void* const* d_in, const int* in_sizes, int n_in,
                              void* d_out, int out_size) {
    const float* pcf = (const float*)d_in[0];
    const float* plm = (const float*)d_in[1];
    const float* emb = (const float*)d_in[2];
    float* out = (float*)d_out;

    const int SC_SMEM = 16384 * 4;   // 64 KB
    cudaFuncSetAttribute(k_scode_mma, cudaFuncAttributeMaxDynamicSharedMemorySize, SC_SMEM);

    k_init<<<256, 256>>>(pcf, plm);
    k_rownorm<<<4096, 256>>>(emb, KS*MN, 0, 0);
    k_rownorm<<<512, 256>>>(pcf, BN, 1, 0);
    k_rownorm<<<512, 256>>>(plm, BN, 1, BN);

    for (int s = 0; s < KS; s++) {
        k_resetmin<<<32, 256>>>();
        k_rownorm<<<1024, 256>>>(nullptr, 2*BN, 2, 0);
        k_argmin<<<dim3(128, 64, 2), 256>>>(emb, s);
        k_update<<<1024, 256>>>(emb, s);
    }

    k_scores<<<dim3(128, 64, 2), 256>>>(emb, pcf, plm);
    k_softmax<<<dim3(BN, 2), 256>>>();
    k_scode_mma<<<1024, 256, SC_SMEM>>>();
    k_rowratio<<<BN, 256>>>();

    k_quant<<<QN/256, 256>>>(pcf, plm, out);
    k_ids<<<(2*BN*KS)/256, 256>>>(out);
    k_mse<<<256, 256>>>(pcf, plm, out);
    k_perp<<<8, 256>>>(out);
    k_final<<<1, 256>>>(out);
}

// round 10
// speedup vs baseline: 4.8733x; 1.9272x over previous
#include <cuda_runtime.h>
#include <cuda_bf16.h>
#include <cstdint>

#define BN 4096
#define DN 128
#define MN 8192
#define KS 4
#define QN (2*BN*DN)
#define HALFQ (BN*DN)
#define OFF_LOSS 1048576
#define OFF_IDS  1048577
#define OFF_PERP 1081345

typedef unsigned long long ull;

// ---------- device scratch ----------
__device__ float g_Enorm[KS*MN];
__device__ float g_xnorm0[2*BN];
__device__ float g_xnormR[2*BN];
__device__ float g_res[QN];
__device__ float g_q[QN];
__device__ ull   g_min[2*BN];
__device__ int   g_counts[KS*2*MN];
__device__ int   g_idx[2*BN*KS];
__device__ float g_ph[2ull*BN*MN];                     // fp32 scores (pre-softmax)
__device__ __align__(16) __nv_bfloat16 g_phh[2ull*BN*MN];  // bf16 probs
__device__ __align__(16) __nv_bfloat16 g_lgh[2ull*BN*MN];  // bf16 log-probs
__device__ float g_Sc[(size_t)BN*BN];
__device__ unsigned g_minkey;
__device__ float g_rowlog[BN];
__device__ float g_mse[256*4];

// ---------- helpers ----------
__device__ __forceinline__ unsigned sortkey(float v) {
    unsigned u = __float_as_uint(v);
    return (u & 0x80000000u) ? ~u : (u | 0x80000000u);
}
__device__ __forceinline__ float unsortkey(unsigned k) {
    return (k & 0x80000000u) ? __uint_as_float(k & 0x7FFFFFFFu)
                             : __uint_as_float(~k);
}
__device__ __forceinline__ ull packdi(float v, int idx) {
    return ((ull)sortkey(v) << 32) | (unsigned)idx;
}
__device__ __forceinline__ uint32_t smem_u32(const void* p) {
    uint32_t a;
    asm("{ .reg .u64 t; cvta.to.shared.u64 t, %1; cvt.u32.u64 %0, t; }"
        : "=r"(a) : "l"(p));
    return a;
}
__device__ __forceinline__ void ldsm4(uint32_t& r0, uint32_t& r1,
                                      uint32_t& r2, uint32_t& r3, uint32_t a) {
    asm volatile("ldmatrix.sync.aligned.m8n8.x4.shared.b16 {%0,%1,%2,%3}, [%4];"
        : "=r"(r0), "=r"(r1), "=r"(r2), "=r"(r3) : "r"(a));
}
__device__ __forceinline__ void mma_bf16(float* c, uint32_t a0, uint32_t a1,
                                         uint32_t a2, uint32_t a3,
                                         uint32_t b0, uint32_t b1) {
    asm volatile("mma.sync.aligned.m16n8k16.row.col.f32.bf16.bf16.f32 "
        "{%0,%1,%2,%3},{%4,%5,%6,%7},{%8,%9},{%0,%1,%2,%3};"
        : "+f"(c[0]), "+f"(c[1]), "+f"(c[2]), "+f"(c[3])
        : "r"(a0), "r"(a1), "r"(a2), "r"(a3), "r"(b0), "r"(b1));
}
#define CP_ASYNC16(s, g) asm volatile("cp.async.ca.shared.global [%0], [%1], 16;" :: "r"(s), "l"(g))
#define CP_COMMIT()      asm volatile("cp.async.commit_group;" ::: "memory")
#define CP_WAIT1()       asm volatile("cp.async.wait_group 1;" ::: "memory")
#define CP_WAIT0()       asm volatile("cp.async.wait_group 0;" ::: "memory")

// ---------- row norms ----------
__global__ __launch_bounds__(256) void k_rownorm(const float* __restrict__ Xin,
                                                 int nrows, int mode, int off) {
    int w = (blockIdx.x * 256 + threadIdx.x) >> 5;
    int lane = threadIdx.x & 31;
    if (w >= nrows) return;
    const float* X = (mode == 2) ? g_res : Xin;
    float* dst = (mode == 0) ? g_Enorm : ((mode == 1) ? g_xnorm0 : g_xnormR);
    float4 v = reinterpret_cast<const float4*>(X + (size_t)w * DN)[lane];
    float s = v.x*v.x + v.y*v.y + v.z*v.z + v.w*v.w;
    #pragma unroll
    for (int o = 16; o; o >>= 1) s += __shfl_xor_sync(0xFFFFFFFFu, s, o);
    if (lane == 0) dst[off + w] = s;
}

// ---------- init ----------
__global__ __launch_bounds__(256) void k_init(const float* __restrict__ pcf,
                                              const float* __restrict__ plm) {
    int stride = gridDim.x * 256;
    for (int i = blockIdx.x * 256 + threadIdx.x; i < QN; i += stride) {
        g_res[i] = (i < HALFQ) ? pcf[i] : plm[i - HALFQ];
        g_q[i] = 0.0f;
    }
    for (int i = blockIdx.x * 256 + threadIdx.x; i < KS*2*MN; i += stride)
        g_counts[i] = 0;
    if (blockIdx.x == 0 && threadIdx.x == 0) g_minkey = 0xFFFFFFFFu;
}

__global__ __launch_bounds__(256) void k_resetmin() {
    int i = blockIdx.x * 256 + threadIdx.x;
    if (i < 2*BN) g_min[i] = 0xFFFFFFFFFFFFFFFFull;
}

// ---------- argmin distance GEMM (exact fp32), 128x64 tile, 8x4/thread ----------
// dynamic smem: resS[128*65] + eS[64*65]  (49920 B)
__global__ __launch_bounds__(256) void k_argmin(const float* __restrict__ emb, int stage) {
    extern __shared__ __align__(16) float sm_a[];
    float* resS = sm_a;              // 128*65
    float* eS   = sm_a + 128*65;     // 64*65
    const int tid = threadIdx.x;
    const int tx = tid & 15, ty = tid >> 4;
    const int stream = blockIdx.z;
    const int b0 = blockIdx.y * 128;
    const int m0 = blockIdx.x * 64;
    const float* resp = g_res + (size_t)stream * HALFQ;
    const float* Ep = emb + (size_t)stage * MN * DN;
    const float* En = g_Enorm + stage * MN;

    float xn[8];
    #pragma unroll
    for (int i = 0; i < 8; i++) xn[i] = g_xnormR[stream*BN + b0 + 8*ty + i];

    float acc[8][4];
    #pragma unroll
    for (int i = 0; i < 8; i++)
        #pragma unroll
        for (int j = 0; j < 4; j++) acc[i][j] = 0.0f;

    for (int dc = 0; dc < 2; dc++) {
        #pragma unroll
        for (int k = 0; k < 32; k++) {
            int e = tid + 256*k; int r = e >> 6; int dd = e & 63;
            resS[r*65 + dd] = resp[(size_t)(b0 + r)*DN + dc*64 + dd];
        }
        #pragma unroll
        for (int k = 0; k < 16; k++) {
            int e = tid + 256*k; int r = e >> 6; int dd = e & 63;
            eS[r*65 + dd] = Ep[(size_t)(m0 + r)*DN + dc*64 + dd];
        }
        __syncthreads();
        #pragma unroll
        for (int d = 0; d < 64; d++) {
            float a[8], bb[4];
            #pragma unroll
            for (int i = 0; i < 8; i++) a[i] = resS[(8*ty+i)*65 + d];
            #pragma unroll
            for (int j = 0; j < 4; j++) bb[j] = eS[(tx+16*j)*65 + d];
            #pragma unroll
            for (int i = 0; i < 8; i++)
                #pragma unroll
                for (int j = 0; j < 4; j++) acc[i][j] += a[i]*bb[j];
        }
        __syncthreads();
    }
    ull* red = (ull*)eS;   // 128*16*8 = 16384 B fits
    #pragma unroll
    for (int i = 0; i < 8; i++) {
        float best = 3.4e38f; int bidx = 0;
        #pragma unroll
        for (int j = 0; j < 4; j++) {
            int mcol = m0 + tx + 16*j;
            float val = (En[mcol] + xn[i]) - 2.0f*acc[i][j];
            if (val < best) { best = val; bidx = mcol; }
        }
        red[(8*ty+i)*16 + tx] = packdi(best, bidx);
    }
    __syncthreads();
    if (tid < 128) {
        ull kk = red[tid*16];
        #pragma unroll
        for (int t = 1; t < 16; t++) { ull c = red[tid*16 + t]; if (c < kk) kk = c; }
        atomicMin(&g_min[(size_t)stream*BN + b0 + tid], kk);
    }
}

// ---------- gather + residual/q update + histogram ----------
__global__ __launch_bounds__(256) void k_update(const float* __restrict__ emb, int stage) {
    int w = (blockIdx.x * 256 + threadIdx.x) >> 5;
    int lane = threadIdx.x & 31;
    if (w >= 2*BN) return;
    int stream = w >> 12; int b = w & (BN - 1);
    int idx = (int)(g_min[w] & 0xFFFFFFFFull);
    float4 e = reinterpret_cast<const float4*>(emb + ((size_t)stage*MN + idx)*DN)[lane];
    float4* qp = reinterpret_cast<float4*>(g_q + (size_t)w*DN);
    float4* rp = reinterpret_cast<float4*>(g_res + (size_t)w*DN);
    float4 q = qp[lane]; q.x += e.x; q.y += e.y; q.z += e.z; q.w += e.w; qp[lane] = q;
    float4 r = rp[lane]; r.x -= e.x; r.y -= e.y; r.z -= e.z; r.w -= e.w; rp[lane] = r;
    if (lane == 0) {
        g_idx[stream*BN*KS + b*KS + stage] = idx;
        atomicAdd(&g_counts[(stage*2 + stream)*MN + idx], 1);
    }
}

// ---------- cmcm scores (fp32, R5-proven) ----------
__global__ __launch_bounds__(256) void k_scores(const float* __restrict__ emb,
                                                const float* __restrict__ pcf,
                                                const float* __restrict__ plm) {
    __shared__ __align__(16) float xS[64*65];
    __shared__ __align__(16) float eS[64*65];
    const int tid = threadIdx.x;
    const int tx = tid & 15, ty = tid >> 4;
    const int stream = blockIdx.z;
    const int b0 = blockIdx.y * 64;
    const int m0 = blockIdx.x * 64;
    const float* Xp = (stream == 0) ? pcf : plm;
    const float* Ep = emb + (size_t)(KS-1) * MN * DN;
    const float* En = g_Enorm + (KS-1)*MN;

    float xn[4];
    #pragma unroll
    for (int i = 0; i < 4; i++) xn[i] = g_xnorm0[stream*BN + b0 + 4*ty + i];

    float acc[4][4];
    #pragma unroll
    for (int i = 0; i < 4; i++)
        #pragma unroll
        for (int j = 0; j < 4; j++) acc[i][j] = 0.0f;

    for (int dc = 0; dc < 2; dc++) {
        #pragma unroll
        for (int k = 0; k < 16; k++) {
            int e = tid + 256*k; int r = e >> 6; int dd = e & 63;
            xS[r*65 + dd] = Xp[(size_t)(b0 + r)*DN + dc*64 + dd];
            eS[r*65 + dd] = Ep[(size_t)(m0 + r)*DN + dc*64 + dd];
        }
        __syncthreads();
        #pragma unroll
        for (int d = 0; d < 64; d++) {
            float a[4], bb[4];
            #pragma unroll
            for (int i = 0; i < 4; i++) a[i] = xS[(4*ty+i)*65 + d];
            #pragma unroll
            for (int j = 0; j < 4; j++) bb[j] = eS[(tx+16*j)*65 + d];
            #pragma unroll
            for (int i = 0; i < 4; i++)
                #pragma unroll
                for (int j = 0; j < 4; j++) acc[i][j] += a[i]*bb[j];
        }
        __syncthreads();
    }
    #pragma unroll
    for (int j = 0; j < 4; j++) {
        int mcol = m0 + tx + 16*j;
        float en = En[mcol];
        #pragma unroll
        for (int i = 0; i < 4; i++) {
            float val = fmaxf((en + xn[i]) - 2.0f*acc[i][j], 0.0f);
            g_ph[(size_t)stream*BN*MN + (size_t)(b0 + 4*ty + i)*MN + mcol] = -sqrtf(val);
        }
    }
}

// ---------- row softmax + log -> bf16 outputs ----------
__global__ __launch_bounds__(256) void k_softmax() {
    __shared__ __align__(16) float srow[MN];
    __shared__ float red[256];
    int b = blockIdx.x, s = blockIdx.y, tid = threadIdx.x;
    size_t base = (size_t)s*BN*MN + (size_t)b*MN;
    const float4* src = reinterpret_cast<const float4*>(g_ph + base);
    float mx = -3.4e38f;
    #pragma unroll
    for (int k = 0; k < 8; k++) {
        float4 v = src[tid + 256*k];
        reinterpret_cast<float4*>(srow)[tid + 256*k] = v;
        mx = fmaxf(mx, fmaxf(fmaxf(v.x, v.y), fmaxf(v.z, v.w)));
    }
    red[tid] = mx; __syncthreads();
    for (int o = 128; o > 0; o >>= 1) {
        if (tid < o) red[tid] = fmaxf(red[tid], red[tid + o]);
        __syncthreads();
    }
    mx = red[0]; __syncthreads();
    float sum = 0.0f;
    #pragma unroll
    for (int k = 0; k < 8; k++) {
        float4 v = reinterpret_cast<float4*>(srow)[tid + 256*k];
        v.x = expf(v.x - mx); v.y = expf(v.y - mx);
        v.z = expf(v.z - mx); v.w = expf(v.w - mx);
        reinterpret_cast<float4*>(srow)[tid + 256*k] = v;
        sum += v.x + v.y + v.z + v.w;
    }
    red[tid] = sum; __syncthreads();
    for (int o = 128; o > 0; o >>= 1) {
        if (tid < o) red[tid] = red[tid] + red[tid + o];
        __syncthreads();
    }
    sum = red[0];
    __nv_bfloat162* dph = reinterpret_cast<__nv_bfloat162*>(g_phh + base);
    __nv_bfloat162* dlg = reinterpret_cast<__nv_bfloat162*>(g_lgh + base);
    #pragma unroll
    for (int k = 0; k < 8; k++) {
        float4 v = reinterpret_cast<float4*>(srow)[tid + 256*k];
        v.x /= sum; v.y /= sum; v.z /= sum; v.w /= sum;
        int p = (tid + 256*k) * 2;
        dph[p]   = __floats2bfloat162_rn(v.x, v.y);
        dph[p+1] = __floats2bfloat162_rn(v.z, v.w);
        dlg[p]   = __floats2bfloat162_rn(logf(v.x + 1e-10f), logf(v.y + 1e-10f));
        dlg[p+1] = __floats2bfloat162_rn(logf(v.z + 1e-10f), logf(v.w + 1e-10f));
    }
}

// ---------- Scode via bf16 mma.m16n8k16, ldmatrix, cp.async double buffer ----------
// CTA: 128x128 C-tile; 8 warps = 4(M) x 2(N); warp 32x64. K-chunk 32.
// smem tile: 128 rows x 80B (64B data + 16B pad) = 10240 B; 4 tiles/buffer, 2 buffers.
#define SCT 10240
#define SCBUF (4*SCT)
__global__ __launch_bounds__(256) void k_scode_bf16() {
    extern __shared__ __align__(16) char smc[];
    const uint32_t sb = smem_u32(smc);
    const int tid = threadIdx.x;
    const int lane = tid & 31, wid = tid >> 5;
    const int wy = wid & 3, wx = wid >> 2;
    const int i0 = (blockIdx.x & 31) * 128;
    const int j0 = (blockIdx.x >> 5) * 128;
    const __nv_bfloat16* A1g = g_phh + (size_t)i0 * MN;                    // Ppcf
    const __nv_bfloat16* A2g = g_phh + (size_t)BN*MN + (size_t)i0 * MN;    // Pplm
    const __nv_bfloat16* B1g = g_lgh + (size_t)BN*MN + (size_t)j0 * MN;    // Lplm
    const __nv_bfloat16* B2g = g_lgh + (size_t)j0 * MN;                    // Lpcf

    float acc[2][8][4];
    #pragma unroll
    for (int mi = 0; mi < 2; mi++)
        #pragma unroll
        for (int n8 = 0; n8 < 8; n8++)
            #pragma unroll
            for (int c = 0; c < 4; c++) acc[mi][n8][c] = 0.0f;

    // ldmatrix per-lane address components
    const int m = lane >> 3, l7 = lane & 7;
    const uint32_t aoff = (uint32_t)(((m & 1)*8 + l7) * 80 + (m >> 1) * 16);
    const uint32_t boff = (uint32_t)(((m >> 1)*8 + l7) * 80 + (m & 1) * 16);

    // stage chunk kc into buffer bsel
    auto stage = [&](int kc, int bsel) {
        int kb = kc * 32;
        uint32_t d0 = sb + bsel * SCBUF;
        #pragma unroll
        for (int it = 0; it < 8; it++) {
            int t = tid + it*256;
            int mat = t >> 9, r = (t >> 2) & 127, c = t & 3;
            const __nv_bfloat16* srcp = (mat == 0) ? A1g : (mat == 1) ? A2g
                                      : (mat == 2) ? B1g : B2g;
            const void* g = srcp + (size_t)r*MN + kb + c*8;
            uint32_t sdst = d0 + mat*SCT + r*80 + c*16;
            CP_ASYNC16(sdst, g);
        }
        CP_COMMIT();
    };

    stage(0, 0);
    for (int kc = 0; kc < 256; kc++) {
        if (kc + 1 < 256) { stage(kc + 1, (kc + 1) & 1); CP_WAIT1(); }
        else CP_WAIT0();
        __syncthreads();
        uint32_t base = sb + (kc & 1) * SCBUF;
        #pragma unroll
        for (int s = 0; s < 2; s++) {
            #pragma unroll
            for (int g = 0; g < 2; g++) {
                uint32_t ab = base + g*SCT + (wy*32)*80 + s*32 + aoff;
                uint32_t a0[2], a1[2], a2[2], a3[2];
                #pragma unroll
                for (int mi = 0; mi < 2; mi++)
                    ldsm4(a0[mi], a1[mi], a2[mi], a3[mi], ab + mi*16*80);
                uint32_t bbase = base + (2 + g)*SCT + (wx*64)*80 + s*32 + boff;
                #pragma unroll
                for (int gg = 0; gg < 4; gg++) {
                    uint32_t b0, b1, b2, b3;
                    ldsm4(b0, b1, b2, b3, bbase + gg*16*80);
                    #pragma unroll
                    for (int mi = 0; mi < 2; mi++) {
                        mma_bf16(acc[mi][gg*2+0], a0[mi], a1[mi], a2[mi], a3[mi], b0, b1);
                        mma_bf16(acc[mi][gg*2+1], a0[mi], a1[mi], a2[mi], a3[mi], b2, b3);
                    }
                }
            }
        }
        __syncthreads();
    }
    // epilogue: store + fused global min
    float lmin = 3.4e38f;
    #pragma unroll
    for (int mi = 0; mi < 2; mi++) {
        int row = i0 + wy*32 + mi*16 + (lane >> 2);
        #pragma unroll
        for (int n8 = 0; n8 < 8; n8++) {
            int col = j0 + wx*64 + n8*8 + (lane & 3)*2;
            float* c = acc[mi][n8];
            *(float2*)&g_Sc[(size_t)row*BN + col]     = make_float2(c[0], c[1]);
            *(float2*)&g_Sc[(size_t)(row+8)*BN + col] = make_float2(c[2], c[3]);
            lmin = fminf(lmin, fminf(fminf(c[0], c[1]), fminf(c[2], c[3])));
        }
    }
    float* red = (float*)smc;
    red[tid] = lmin; __syncthreads();
    for (int o = 128; o > 0; o >>= 1) {
        if (tid < o) red[tid] = fminf(red[tid], red[tid + o]);
        __syncthreads();
    }
    if (tid == 0) atomicMin(&g_minkey, sortkey(red[0]));
}

// ---------- per-row: log(diag(E)/(rowsum(E)+eps)) ----------
__global__ __launch_bounds__(256) void k_rowratio() {
    __shared__ float red[256];
    int i = blockIdx.x, tid = threadIdx.x;
    float Mx = -unsortkey(g_minkey);
    const float* row = g_Sc + (size_t)i * BN;
    float sum = 0.0f;
    #pragma unroll
    for (int k = 0; k < 16; k++) sum += expf(row[tid + 256*k] + Mx);
    red[tid] = sum; __syncthreads();
    for (int o = 128; o > 0; o >>= 1) {
        if (tid < o) red[tid] = red[tid] + red[tid + o];
        __syncthreads();
    }
    if (tid == 0) {
        float ratio = expf(row[i] + Mx) / (red[0] + 1e-5f);
        g_rowlog[i] = logf(ratio);
    }
}

// ---------- quantized = fl(x + fl(q - x)) ----------
__global__ __launch_bounds__(256) void k_quant(const float* __restrict__ pcf,
                                               const float* __restrict__ plm,
                                               float* __restrict__ out) {
    int e = blockIdx.x * 256 + threadIdx.x;
    if (e >= QN) return;
    float x = (e < HALFQ) ? pcf[e] : plm[e - HALFQ];
    float t = g_q[e] - x;
    out[e] = x + t;
}

__global__ __launch_bounds__(256) void k_ids(float* __restrict__ out) {
    int e = blockIdx.x * 256 + threadIdx.x;
    if (e < 2*BN*KS) out[OFF_IDS + e] = (float)g_idx[e];
}

__global__ __launch_bounds__(256) void k_mse(const float* __restrict__ pcf,
                                             const float* __restrict__ plm,
                                             const float* __restrict__ out) {
    __shared__ float red[256];
    int tid = threadIdx.x, bid = blockIdx.x;
    float s[4] = {0.f, 0.f, 0.f, 0.f};
    #pragma unroll
    for (int k = 0; k < 8; k++) {
        int e = bid*2048 + k*256 + tid;
        float qp = out[e], qm = out[HALFQ + e];
        float xp = pcf[e], xm = plm[e];
        float d;
        d = xp - qp; s[0] += d*d;
        d = xp - qm; s[1] += d*d;
        d = xm - qm; s[2] += d*d;
        d = xm - qp; s[3] += d*d;
    }
    #pragma unroll
    for (int c = 0; c < 4; c++) {
        red[tid] = s[c]; __syncthreads();
        for (int o = 128; o > 0; o >>= 1) {
            if (tid < o) red[tid] = red[tid] + red[tid + o];
            __syncthreads();
        }
        if (tid == 0) g_mse[bid*4 + c] = red[0];
        __syncthreads();
    }
}

__global__ __launch_bounds__(256) void k_perp(float* __restrict__ out) {
    __shared__ float red[256];
    int b = blockIdx.x, tid = threadIdx.x;
    int k = b >> 1, s = b & 1;
    const int* cnt = g_counts + (k*2 + s)*MN;
    float sum = 0.0f;
    #pragma unroll
    for (int t = 0; t < 32; t++) {
        float avg = (float)cnt[tid + 256*t] / (float)BN;
        sum += avg * logf(avg + 1e-10f);
    }
    red[tid] = sum; __syncthreads();
    for (int o = 128; o > 0; o >>= 1) {
        if (tid < o) red[tid] = red[tid] + red[tid + o];
        __syncthreads();
    }
    if (tid == 0) out[OFF_PERP + k*2 + s] = expf(-red[0]);
}

__global__ __launch_bounds__(256) void k_final(float* __restrict__ out) {
    __shared__ float red[256];
    int tid = threadIdx.x;
    float s = 0.0f;
    #pragma unroll
    for (int k = 0; k < 16; k++) s += g_rowlog[tid + 256*k];
    red[tid] = s; __syncthreads();
    for (int o = 128; o > 0; o >>= 1) {
        if (tid < o) red[tid] = red[tid] + red[tid + o];
        __syncthreads();
    }
    float Lc = -(red[0] / (float)BN);
    __syncthreads();
    float m[4];
    for (int c = 0; c < 4; c++) {
        red[tid] = g_mse[tid*4 + c]; __syncthreads();
        for (int o = 128; o > 0; o >>= 1) {
            if (tid < o) red[tid] = red[tid] + red[tid + o];
            __syncthreads();
        }
        m[c] = red[0] / (float)HALFQ;
        __syncthreads();
    }
    if (tid == 0) {
        float pcf_loss = 0.5f*m[0] + 0.25f*m[1];
        float plm_loss = 0.5f*m[2] + 0.25f*m[3];
        out[OFF_LOSS] = 0.5f*Lc + pcf_loss + plm_loss;
    }
}

// ---------- orchestration ----------
extern "C" void kernel_launch(void* const* d_in, const int* in_sizes, int n_in,
                              void* d_out, int out_size) {
    const float* pcf = (const float*)d_in[0];
    const float* plm = (const float*)d_in[1];
    const float* emb = (const float*)d_in[2];
    float* out = (float*)d_out;

    const int SM_ARG = (128*65 + 64*65) * 4;   // 49920
    const int SM_SC  = 2 * SCBUF;              // 81920
    cudaFuncSetAttribute(k_argmin, cudaFuncAttributeMaxDynamicSharedMemorySize, SM_ARG);
    cudaFuncSetAttribute(k_scode_bf16, cudaFuncAttributeMaxDynamicSharedMemorySize, SM_SC);

    k_init<<<256, 256>>>(pcf, plm);
    k_rownorm<<<4096, 256>>>(emb, KS*MN, 0, 0);
    k_rownorm<<<512, 256>>>(pcf, BN, 1, 0);
    k_rownorm<<<512, 256>>>(plm, BN, 1, BN);

    for (int s = 0; s < KS; s++) {
        k_resetmin<<<32, 256>>>();
        k_rownorm<<<1024, 256>>>(nullptr, 2*BN, 2, 0);
        k_argmin<<<dim3(128, 32, 2), 256, SM_ARG>>>(emb, s);
        k_update<<<1024, 256>>>(emb, s);
    }

    k_scores<<<dim3(128, 64, 2), 256>>>(emb, pcf, plm);
    k_softmax<<<dim3(BN, 2), 256>>>();
    k_scode_bf16<<<1024, 256, SM_SC>>>();
    k_rowratio<<<BN, 256>>>();

    k_quant<<<QN/256, 256>>>(pcf, plm, out);
    k_ids<<<(2*BN*KS)/256, 256>>>(out);
    k_mse<<<256, 256>>>(pcf, plm, out);
    k_perp<<<8, 256>>>(out);
    k_final<<<1, 256>>>(out);
}

// round 12
// speedup vs baseline: 5.2831x; 1.0841x over previous
#include <cuda_runtime.h>
#include <cuda_bf16.h>
#include <cstdint>

#define BN 4096
#define DN 128
#define MN 8192
#define KS 4
#define QN (2*BN*DN)
#define HALFQ (BN*DN)
#define OFF_LOSS 1048576
#define OFF_IDS  1048577
#define OFF_PERP 1081345

typedef unsigned long long ull;

// ---------- device scratch ----------
__device__ float g_Enorm[KS*MN];
__device__ float g_xnorm0[2*BN];
__device__ float g_xnormR[2*BN];
__device__ float g_res[QN];
__device__ float g_q[QN];
__device__ ull   g_min[2*BN];
__device__ int   g_counts[KS*2*MN];
__device__ int   g_idx[2*BN*KS];
__device__ float g_ph[2ull*BN*MN];
__device__ __align__(16) __nv_bfloat16 g_phh[2ull*BN*MN];
__device__ __align__(16) __nv_bfloat16 g_lgh[2ull*BN*MN];
__device__ float g_Sc[(size_t)BN*BN];
__device__ unsigned g_minkey;
__device__ float g_rowlog[BN];
__device__ float g_mse[256*4];

// ---------- helpers ----------
__device__ __forceinline__ unsigned sortkey(float v) {
    unsigned u = __float_as_uint(v);
    return (u & 0x80000000u) ? ~u : (u | 0x80000000u);
}
__device__ __forceinline__ float unsortkey(unsigned k) {
    return (k & 0x80000000u) ? __uint_as_float(k & 0x7FFFFFFFu)
                             : __uint_as_float(~k);
}
__device__ __forceinline__ ull packdi(float v, int idx) {
    return ((ull)sortkey(v) << 32) | (unsigned)idx;
}
__device__ __forceinline__ uint32_t smem_u32(const void* p) {
    uint32_t a;
    asm("{ .reg .u64 t; cvta.to.shared.u64 t, %1; cvt.u32.u64 %0, t; }"
        : "=r"(a) : "l"(p));
    return a;
}
__device__ __forceinline__ float tf32r(float x) {
    float r;
    asm("{\n\t.reg .b32 t;\n\tcvt.rna.tf32.f32 t, %1;\n\tmov.b32 %0, t;\n\t}"
        : "=f"(r) : "f"(x));
    return r;
}
__device__ __forceinline__ void mma_t(float* c, uint32_t a0, uint32_t a1,
                                      uint32_t a2, uint32_t a3,
                                      uint32_t b0, uint32_t b1) {
    asm volatile("mma.sync.aligned.m16n8k8.row.col.f32.tf32.tf32.f32 "
        "{%0,%1,%2,%3},{%4,%5,%6,%7},{%8,%9},{%0,%1,%2,%3};"
        : "+f"(c[0]), "+f"(c[1]), "+f"(c[2]), "+f"(c[3])
        : "r"(a0), "r"(a1), "r"(a2), "r"(a3), "r"(b0), "r"(b1));
}
__device__ __forceinline__ void ldsm4(uint32_t& r0, uint32_t& r1,
                                      uint32_t& r2, uint32_t& r3, uint32_t a) {
    asm volatile("ldmatrix.sync.aligned.m8n8.x4.shared.b16 {%0,%1,%2,%3}, [%4];"
        : "=r"(r0), "=r"(r1), "=r"(r2), "=r"(r3) : "r"(a));
}
__device__ __forceinline__ void mma_bf16(float* c, uint32_t a0, uint32_t a1,
                                         uint32_t a2, uint32_t a3,
                                         uint32_t b0, uint32_t b1) {
    asm volatile("mma.sync.aligned.m16n8k16.row.col.f32.bf16.bf16.f32 "
        "{%0,%1,%2,%3},{%4,%5,%6,%7},{%8,%9},{%0,%1,%2,%3};"
        : "+f"(c[0]), "+f"(c[1]), "+f"(c[2]), "+f"(c[3])
        : "r"(a0), "r"(a1), "r"(a2), "r"(a3), "r"(b0), "r"(b1));
}
#define CP_ASYNC16(s, g) asm volatile("cp.async.ca.shared.global [%0], [%1], 16;" :: "r"(s), "l"(g))
#define CP_COMMIT()      asm volatile("cp.async.commit_group;" ::: "memory")
#define CP_WAIT1()       asm volatile("cp.async.wait_group 1;" ::: "memory")
#define CP_WAIT0()       asm volatile("cp.async.wait_group 0;" ::: "memory")

// ---------- row norms: mode 0 -> g_Enorm ; mode 3 -> g_xnorm0 AND g_xnormR ----------
__global__ __launch_bounds__(256) void k_rownorm(const float* __restrict__ Xin,
                                                 int nrows, int mode, int off) {
    int w = (blockIdx.x * 256 + threadIdx.x) >> 5;
    int lane = threadIdx.x & 31;
    if (w >= nrows) return;
    float4 v = reinterpret_cast<const float4*>(Xin + (size_t)w * DN)[lane];
    float s = v.x*v.x + v.y*v.y + v.z*v.z + v.w*v.w;
    #pragma unroll
    for (int o = 16; o; o >>= 1) s += __shfl_xor_sync(0xFFFFFFFFu, s, o);
    if (lane == 0) {
        if (mode == 0) g_Enorm[off + w] = s;
        else { g_xnorm0[off + w] = s; g_xnormR[off + w] = s; }
    }
}

// ---------- init ----------
__global__ __launch_bounds__(256) void k_init(const float* __restrict__ pcf,
                                              const float* __restrict__ plm) {
    int stride = gridDim.x * 256;
    for (int i = blockIdx.x * 256 + threadIdx.x; i < QN; i += stride) {
        g_res[i] = (i < HALFQ) ? pcf[i] : plm[i - HALFQ];
        g_q[i] = 0.0f;
    }
    for (int i = blockIdx.x * 256 + threadIdx.x; i < KS*2*MN; i += stride)
        g_counts[i] = 0;
    for (int i = blockIdx.x * 256 + threadIdx.x; i < 2*BN; i += stride)
        g_min[i] = 0xFFFFFFFFFFFFFFFFull;
    if (blockIdx.x == 0 && threadIdx.x == 0) g_minkey = 0xFFFFFFFFu;
}

// ---------- argmin distance GEMM: EXACT fp32 scalar chain (frozen R5/R10 arithmetic) ----------
// 128(b) x 128(m) tile, 8x8 per thread. Chain per (row,col): dc 0..1, d 0..63 ascending.
// dynamic smem: resS[128*65] + eS[128*65] = 66560 B
__global__ __launch_bounds__(256) void k_argmin(const float* __restrict__ emb, int stage) {
    extern __shared__ __align__(16) float sm_a[];
    float* resS = sm_a;              // 128*65
    float* eS   = sm_a + 128*65;     // 128*65
    const int tid = threadIdx.x;
    const int tx = tid & 15, ty = tid >> 4;
    const int stream = blockIdx.z;
    const int b0 = blockIdx.y * 128;
    const int m0 = blockIdx.x * 128;
    const float* resp = g_res + (size_t)stream * HALFQ;
    const float* Ep = emb + (size_t)stage * MN * DN;
    const float* En = g_Enorm + stage * MN;

    float xn[8];
    #pragma unroll
    for (int i = 0; i < 8; i++) xn[i] = g_xnormR[stream*BN + b0 + 8*ty + i];

    float acc[8][8];
    #pragma unroll
    for (int i = 0; i < 8; i++)
        #pragma unroll
        for (int j = 0; j < 8; j++) acc[i][j] = 0.0f;

    for (int dc = 0; dc < 2; dc++) {
        #pragma unroll
        for (int k = 0; k < 32; k++) {
            int e = tid + 256*k; int r = e >> 6; int dd = e & 63;
            resS[r*65 + dd] = resp[(size_t)(b0 + r)*DN + dc*64 + dd];
        }
        #pragma unroll
        for (int k = 0; k < 32; k++) {
            int e = tid + 256*k; int r = e >> 6; int dd = e & 63;
            eS[r*65 + dd] = Ep[(size_t)(m0 + r)*DN + dc*64 + dd];
        }
        __syncthreads();
        #pragma unroll
        for (int d = 0; d < 64; d++) {
            float a[8], bb[8];
            #pragma unroll
            for (int i = 0; i < 8; i++) a[i] = resS[(8*ty+i)*65 + d];
            #pragma unroll
            for (int j = 0; j < 8; j++) bb[j] = eS[(tx+16*j)*65 + d];
            #pragma unroll
            for (int i = 0; i < 8; i++)
                #pragma unroll
                for (int j = 0; j < 8; j++) acc[i][j] += a[i]*bb[j];
        }
        __syncthreads();
    }
    ull* red = (ull*)eS;   // 128*16*8 = 16384 B, reused post-sync
    #pragma unroll
    for (int i = 0; i < 8; i++) {
        float best = 3.4e38f; int bidx = 0;
        #pragma unroll
        for (int j = 0; j < 8; j++) {
            int mcol = m0 + tx + 16*j;
            float val = (En[mcol] + xn[i]) - 2.0f*acc[i][j];
            if (val < best) { best = val; bidx = mcol; }
        }
        red[(8*ty+i)*16 + tx] = packdi(best, bidx);
    }
    __syncthreads();
    if (tid < 128) {
        ull kk = red[tid*16];
        #pragma unroll
        for (int t = 1; t < 16; t++) { ull c = red[tid*16 + t]; if (c < kk) kk = c; }
        atomicMin(&g_min[(size_t)stream*BN + b0 + tid], kk);
    }
}

// ---------- cmcm scores via 3xTF32 tensor cores (values only, feeds softmax) ----------
// CTA tile 128(b) x 128(m); 8 warps = 4(b) x 2(m). K=128 in 4 chunks of 32.
__global__ __launch_bounds__(256) void k_scorestc(const float* __restrict__ emb) {
    __shared__ __align__(16) float sA[128*36];
    __shared__ __align__(16) float sB[128*36];
    const int tid = threadIdx.x;
    const int lane = tid & 31, wid = tid >> 5;
    const int wy = wid & 3, wx = wid >> 2;
    const int stream = blockIdx.z;
    const int b0 = blockIdx.y * 128;
    const int m0 = blockIdx.x * 128;
    const float* resp = g_res + (size_t)stream * HALFQ;   // == original inputs (pre-update)
    const float* Ep = emb + (size_t)(KS-1) * MN * DN;
    const float* En = g_Enorm + (KS-1)*MN;
    const float* xnorm = g_xnorm0 + stream * BN;

    float acc[2][8][4];
    #pragma unroll
    for (int mt = 0; mt < 2; mt++)
        #pragma unroll
        for (int n8 = 0; n8 < 8; n8++)
            #pragma unroll
            for (int c = 0; c < 4; c++) acc[mt][n8][c] = 0.0f;

    const uint32_t sAu = smem_u32(sA), sBu = smem_u32(sB);
    const int l4 = lane >> 2, l3 = lane & 3;

    for (int chk = 0; chk < 4; chk++) {
        int kb = chk * 32;
        #pragma unroll
        for (int i = 0; i < 4; i++) {
            int v = tid + i*256;
            int row = v >> 3, c4 = (v & 7) * 4;
            CP_ASYNC16(sAu + (uint32_t)(row*36 + c4)*4,
                       resp + (size_t)(b0 + row)*DN + kb + c4);
        }
        #pragma unroll
        for (int i = 0; i < 4; i++) {
            int v = tid + i*256;
            int row = v >> 3, c4 = (v & 7) * 4;
            CP_ASYNC16(sBu + (uint32_t)(row*36 + c4)*4,
                       Ep + (size_t)(m0 + row)*DN + kb + c4);
        }
        CP_COMMIT(); CP_WAIT0();
        __syncthreads();
        #pragma unroll
        for (int k8 = 0; k8 < 4; k8++) {
            const int kk = k8*8 + l3;
            uint32_t aH[2][4], aL[2][4];
            #pragma unroll
            for (int mt = 0; mt < 2; mt++) {
                int r = wy*32 + mt*16 + l4;
                float x0 = sA[r*36 + kk];
                float x1 = sA[(r+8)*36 + kk];
                float x2 = sA[r*36 + kk + 4];
                float x3 = sA[(r+8)*36 + kk + 4];
                float h0 = tf32r(x0), h1 = tf32r(x1), h2 = tf32r(x2), h3 = tf32r(x3);
                aH[mt][0] = __float_as_uint(h0); aL[mt][0] = __float_as_uint(tf32r(x0 - h0));
                aH[mt][1] = __float_as_uint(h1); aL[mt][1] = __float_as_uint(tf32r(x1 - h1));
                aH[mt][2] = __float_as_uint(h2); aL[mt][2] = __float_as_uint(tf32r(x2 - h2));
                aH[mt][3] = __float_as_uint(h3); aL[mt][3] = __float_as_uint(tf32r(x3 - h3));
            }
            #pragma unroll
            for (int n8 = 0; n8 < 8; n8++) {
                int n = wx*64 + n8*8 + l4;
                float y0 = sB[n*36 + kk];
                float y1 = sB[n*36 + kk + 4];
                float g0 = tf32r(y0), g1 = tf32r(y1);
                uint32_t bH0 = __float_as_uint(g0), bH1 = __float_as_uint(g1);
                uint32_t bL0 = __float_as_uint(tf32r(y0 - g0));
                uint32_t bL1 = __float_as_uint(tf32r(y1 - g1));
                #pragma unroll
                for (int mt = 0; mt < 2; mt++) {
                    mma_t(acc[mt][n8], aH[mt][0], aH[mt][1], aH[mt][2], aH[mt][3], bH0, bH1);
                    mma_t(acc[mt][n8], aH[mt][0], aH[mt][1], aH[mt][2], aH[mt][3], bL0, bL1);
                    mma_t(acc[mt][n8], aL[mt][0], aL[mt][1], aL[mt][2], aL[mt][3], bH0, bH1);
                }
            }
        }
        __syncthreads();
    }

    float xv[2][2];
    #pragma unroll
    for (int mt = 0; mt < 2; mt++) {
        xv[mt][0] = xnorm[b0 + wy*32 + mt*16 + l4];
        xv[mt][1] = xnorm[b0 + wy*32 + mt*16 + l4 + 8];
    }
    size_t sbase = (size_t)stream*BN*MN;
    #pragma unroll
    for (int mt = 0; mt < 2; mt++) {
        int r = b0 + wy*32 + mt*16 + l4;
        #pragma unroll
        for (int n8 = 0; n8 < 8; n8++) {
            int c0 = m0 + wx*64 + n8*8 + l3*2;
            float e0 = En[c0], e1 = En[c0+1];
            float* a = acc[mt][n8];
            float2 o0, o1;
            o0.x = -sqrtf(fmaxf((e0 + xv[mt][0]) - 2.0f*a[0], 0.0f));
            o0.y = -sqrtf(fmaxf((e1 + xv[mt][0]) - 2.0f*a[1], 0.0f));
            o1.x = -sqrtf(fmaxf((e0 + xv[mt][1]) - 2.0f*a[2], 0.0f));
            o1.y = -sqrtf(fmaxf((e1 + xv[mt][1]) - 2.0f*a[3], 0.0f));
            *(float2*)&g_ph[sbase + (size_t)r*MN + c0]     = o0;
            *(float2*)&g_ph[sbase + (size_t)(r+8)*MN + c0] = o1;
        }
    }
}

// ---------- gather + residual/q update + histogram + norm + min-reset ----------
__global__ __launch_bounds__(256) void k_update(const float* __restrict__ emb, int stage) {
    int w = (blockIdx.x * 256 + threadIdx.x) >> 5;
    int lane = threadIdx.x & 31;
    if (w >= 2*BN) return;
    int stream = w >> 12; int b = w & (BN - 1);
    int idx = (int)(g_min[w] & 0xFFFFFFFFull);
    float4 e = reinterpret_cast<const float4*>(emb + ((size_t)stage*MN + idx)*DN)[lane];
    float4* qp = reinterpret_cast<float4*>(g_q + (size_t)w*DN);
    float4* rp = reinterpret_cast<float4*>(g_res + (size_t)w*DN);
    float4 q = qp[lane]; q.x += e.x; q.y += e.y; q.z += e.z; q.w += e.w; qp[lane] = q;
    float4 r = rp[lane]; r.x -= e.x; r.y -= e.y; r.z -= e.z; r.w -= e.w; rp[lane] = r;
    float s = r.x*r.x + r.y*r.y + r.z*r.z + r.w*r.w;
    #pragma unroll
    for (int o = 16; o; o >>= 1) s += __shfl_xor_sync(0xFFFFFFFFu, s, o);
    if (lane == 0) {
        g_xnormR[w] = s;
        g_idx[stream*BN*KS + b*KS + stage] = idx;
        atomicAdd(&g_counts[(stage*2 + stream)*MN + idx], 1);
        g_min[w] = 0xFFFFFFFFFFFFFFFFull;
    }
}

// ---------- row softmax + log -> bf16 outputs ----------
__global__ __launch_bounds__(256) void k_softmax() {
    __shared__ __align__(16) float srow[MN];
    __shared__ float red[256];
    int b = blockIdx.x, s = blockIdx.y, tid = threadIdx.x;
    size_t base = (size_t)s*BN*MN + (size_t)b*MN;
    const float4* src = reinterpret_cast<const float4*>(g_ph + base);
    float mx = -3.4e38f;
    #pragma unroll
    for (int k = 0; k < 8; k++) {
        float4 v = src[tid + 256*k];
        reinterpret_cast<float4*>(srow)[tid + 256*k] = v;
        mx = fmaxf(mx, fmaxf(fmaxf(v.x, v.y), fmaxf(v.z, v.w)));
    }
    red[tid] = mx; __syncthreads();
    for (int o = 128; o > 0; o >>= 1) {
        if (tid < o) red[tid] = fmaxf(red[tid], red[tid + o]);
        __syncthreads();
    }
    mx = red[0]; __syncthreads();
    float sum = 0.0f;
    #pragma unroll
    for (int k = 0; k < 8; k++) {
        float4 v = reinterpret_cast<float4*>(srow)[tid + 256*k];
        v.x = expf(v.x - mx); v.y = expf(v.y - mx);
        v.z = expf(v.z - mx); v.w = expf(v.w - mx);
        reinterpret_cast<float4*>(srow)[tid + 256*k] = v;
        sum += v.x + v.y + v.z + v.w;
    }
    red[tid] = sum; __syncthreads();
    for (int o = 128; o > 0; o >>= 1) {
        if (tid < o) red[tid] = red[tid] + red[tid + o];
        __syncthreads();
    }
    sum = red[0];
    __nv_bfloat162* dph = reinterpret_cast<__nv_bfloat162*>(g_phh + base);
    __nv_bfloat162* dlg = reinterpret_cast<__nv_bfloat162*>(g_lgh + base);
    #pragma unroll
    for (int k = 0; k < 8; k++) {
        float4 v = reinterpret_cast<float4*>(srow)[tid + 256*k];
        v.x /= sum; v.y /= sum; v.z /= sum; v.w /= sum;
        int p = (tid + 256*k) * 2;
        dph[p]   = __floats2bfloat162_rn(v.x, v.y);
        dph[p+1] = __floats2bfloat162_rn(v.z, v.w);
        dlg[p]   = __floats2bfloat162_rn(logf(v.x + 1e-10f), logf(v.y + 1e-10f));
        dlg[p+1] = __floats2bfloat162_rn(logf(v.z + 1e-10f), logf(v.w + 1e-10f));
    }
}

// ---------- Scode via bf16 mma.m16n8k16, ldmatrix, cp.async double buffer ----------
#define SCT 10240
#define SCBUF (4*SCT)
__global__ __launch_bounds__(256) void k_scode_bf16() {
    extern __shared__ __align__(16) char smc[];
    const uint32_t sb = smem_u32(smc);
    const int tid = threadIdx.x;
    const int lane = tid & 31, wid = tid >> 5;
    const int wy = wid & 3, wx = wid >> 2;
    const int i0 = (blockIdx.x & 31) * 128;
    const int j0 = (blockIdx.x >> 5) * 128;
    const __nv_bfloat16* A1g = g_phh + (size_t)i0 * MN;
    const __nv_bfloat16* A2g = g_phh + (size_t)BN*MN + (size_t)i0 * MN;
    const __nv_bfloat16* B1g = g_lgh + (size_t)BN*MN + (size_t)j0 * MN;
    const __nv_bfloat16* B2g = g_lgh + (size_t)j0 * MN;

    float acc[2][8][4];
    #pragma unroll
    for (int mi = 0; mi < 2; mi++)
        #pragma unroll
        for (int n8 = 0; n8 < 8; n8++)
            #pragma unroll
            for (int c = 0; c < 4; c++) acc[mi][n8][c] = 0.0f;

    const int m = lane >> 3, l7 = lane & 7;
    const uint32_t aoff = (uint32_t)(((m & 1)*8 + l7) * 80 + (m >> 1) * 16);
    const uint32_t boff = (uint32_t)(((m >> 1)*8 + l7) * 80 + (m & 1) * 16);

    auto stage = [&](int kc, int bsel) {
        int kb = kc * 32;
        uint32_t d0 = sb + bsel * SCBUF;
        #pragma unroll
        for (int it = 0; it < 8; it++) {
            int t = tid + it*256;
            int mat = t >> 9, r = (t >> 2) & 127, c = t & 3;
            const __nv_bfloat16* srcp = (mat == 0) ? A1g : (mat == 1) ? A2g
                                      : (mat == 2) ? B1g : B2g;
            const void* g = srcp + (size_t)r*MN + kb + c*8;
            uint32_t sdst = d0 + mat*SCT + r*80 + c*16;
            CP_ASYNC16(sdst, g);
        }
        CP_COMMIT();
    };

    stage(0, 0);
    for (int kc = 0; kc < 256; kc++) {
        if (kc + 1 < 256) { stage(kc + 1, (kc + 1) & 1); CP_WAIT1(); }
        else CP_WAIT0();
        __syncthreads();
        uint32_t base = sb + (kc & 1) * SCBUF;
        #pragma unroll
        for (int s = 0; s < 2; s++) {
            #pragma unroll
            for (int g = 0; g < 2; g++) {
                uint32_t ab = base + g*SCT + (wy*32)*80 + s*32 + aoff;
                uint32_t a0[2], a1[2], a2[2], a3[2];
                #pragma unroll
                for (int mi = 0; mi < 2; mi++)
                    ldsm4(a0[mi], a1[mi], a2[mi], a3[mi], ab + mi*16*80);
                uint32_t bbase = base + (2 + g)*SCT + (wx*64)*80 + s*32 + boff;
                #pragma unroll
                for (int gg = 0; gg < 4; gg++) {
                    uint32_t b0, b1, b2, b3;
                    ldsm4(b0, b1, b2, b3, bbase + gg*16*80);
                    #pragma unroll
                    for (int mi = 0; mi < 2; mi++) {
                        mma_bf16(acc[mi][gg*2+0], a0[mi], a1[mi], a2[mi], a3[mi], b0, b1);
                        mma_bf16(acc[mi][gg*2+1], a0[mi], a1[mi], a2[mi], a3[mi], b2, b3);
                    }
                }
            }
        }
        __syncthreads();
    }
    float lmin = 3.4e38f;
    #pragma unroll
    for (int mi = 0; mi < 2; mi++) {
        int row = i0 + wy*32 + mi*16 + (lane >> 2);
        #pragma unroll
        for (int n8 = 0; n8 < 8; n8++) {
            int col = j0 + wx*64 + n8*8 + (lane & 3)*2;
            float* c = acc[mi][n8];
            *(float2*)&g_Sc[(size_t)row*BN + col]     = make_float2(c[0], c[1]);
            *(float2*)&g_Sc[(size_t)(row+8)*BN + col] = make_float2(c[2], c[3]);
            lmin = fminf(lmin, fminf(fminf(c[0], c[1]), fminf(c[2], c[3])));
        }
    }
    float* red = (float*)smc;
    red[tid] = lmin; __syncthreads();
    for (int o = 128; o > 0; o >>= 1) {
        if (tid < o) red[tid] = fminf(red[tid], red[tid + o]);
        __syncthreads();
    }
    if (tid == 0) atomicMin(&g_minkey, sortkey(red[0]));
}

// ---------- per-row: log(diag(E)/(rowsum(E)+eps)) ----------
__global__ __launch_bounds__(256) void k_rowratio() {
    __shared__ float red[256];
    int i = blockIdx.x, tid = threadIdx.x;
    float Mx = -unsortkey(g_minkey);
    const float* row = g_Sc + (size_t)i * BN;
    float sum = 0.0f;
    #pragma unroll
    for (int k = 0; k < 16; k++) sum += expf(row[tid + 256*k] + Mx);
    red[tid] = sum; __syncthreads();
    for (int o = 128; o > 0; o >>= 1) {
        if (tid < o) red[tid] = red[tid] + red[tid + o];
        __syncthreads();
    }
    if (tid == 0) {
        float ratio = expf(row[i] + Mx) / (red[0] + 1e-5f);
        g_rowlog[i] = logf(ratio);
    }
}

// ---------- quantized = fl(x + fl(q - x)) ----------
__global__ __launch_bounds__(256) void k_quant(const float* __restrict__ pcf,
                                               const float* __restrict__ plm,
                                               float* __restrict__ out) {
    int e = blockIdx.x * 256 + threadIdx.x;
    if (e >= QN) return;
    float x = (e < HALFQ) ? pcf[e] : plm[e - HALFQ];
    float t = g_q[e] - x;
    out[e] = x + t;
}

__global__ __launch_bounds__(256) void k_ids(float* __restrict__ out) {
    int e = blockIdx.x * 256 + threadIdx.x;
    if (e < 2*BN*KS) out[OFF_IDS + e] = (float)g_idx[e];
}

__global__ __launch_bounds__(256) void k_mse(const float* __restrict__ pcf,
                                             const float* __restrict__ plm,
                                             const float* __restrict__ out) {
    __shared__ float red[256];
    int tid = threadIdx.x, bid = blockIdx.x;
    float s[4] = {0.f, 0.f, 0.f, 0.f};
    #pragma unroll
    for (int k = 0; k < 8; k++) {
        int e = bid*2048 + k*256 + tid;
        float qp = out[e], qm = out[HALFQ + e];
        float xp = pcf[e], xm = plm[e];
        float d;
        d = xp - qp; s[0] += d*d;
        d = xp - qm; s[1] += d*d;
        d = xm - qm; s[2] += d*d;
        d = xm - qp; s[3] += d*d;
    }
    #pragma unroll
    for (int c = 0; c < 4; c++) {
        red[tid] = s[c]; __syncthreads();
        for (int o = 128; o > 0; o >>= 1) {
            if (tid < o) red[tid] = red[tid] + red[tid + o];
            __syncthreads();
        }
        if (tid == 0) g_mse[bid*4 + c] = red[0];
        __syncthreads();
    }
}

__global__ __launch_bounds__(256) void k_perp(float* __restrict__ out) {
    __shared__ float red[256];
    int b = blockIdx.x, tid = threadIdx.x;
    int k = b >> 1, s = b & 1;
    const int* cnt = g_counts + (k*2 + s)*MN;
    float sum = 0.0f;
    #pragma unroll
    for (int t = 0; t < 32; t++) {
        float avg = (float)cnt[tid + 256*t] / (float)BN;
        sum += avg * logf(avg + 1e-10f);
    }
    red[tid] = sum; __syncthreads();
    for (int o = 128; o > 0; o >>= 1) {
        if (tid < o) red[tid] = red[tid] + red[tid + o];
        __syncthreads();
    }
    if (tid == 0) out[OFF_PERP + k*2 + s] = expf(-red[0]);
}

__global__ __launch_bounds__(256) void k_final(float* __restrict__ out) {
    __shared__ float red[256];
    int tid = threadIdx.x;
    float s = 0.0f;
    #pragma unroll
    for (int k = 0; k < 16; k++) s += g_rowlog[tid + 256*k];
    red[tid] = s; __syncthreads();
    for (int o = 128; o > 0; o >>= 1) {
        if (tid < o) red[tid] = red[tid] + red[tid + o];
        __syncthreads();
    }
    float Lc = -(red[0] / (float)BN);
    __syncthreads();
    float m[4];
    for (int c = 0; c < 4; c++) {
        red[tid] = g_mse[tid*4 + c]; __syncthreads();
        for (int o = 128; o > 0; o >>= 1) {
            if (tid < o) red[tid] = red[tid] + red[tid + o];
            __syncthreads();
        }
        m[c] = red[0] / (float)HALFQ;
        __syncthreads();
    }
    if (tid == 0) {
        float pcf_loss = 0.5f*m[0] + 0.25f*m[1];
        float plm_loss = 0.5f*m[2] + 0.25f*m[3];
        out[OFF_LOSS] = 0.5f*Lc + pcf_loss + plm_loss;
    }
}

// ---------- orchestration ----------
extern "C" void kernel_launch(void* const* d_in, const int* in_sizes, int n_in,
                              void* d_out, int out_size) {
    const float* pcf = (const float*)d_in[0];
    const float* plm = (const float*)d_in[1];
    const float* emb = (const float*)d_in[2];
    float* out = (float*)d_out;

    const int SM_ARG = 2 * 128 * 65 * 4;   // 66560
    const int SM_SC  = 2 * SCBUF;          // 81920
    cudaFuncSetAttribute(k_argmin, cudaFuncAttributeMaxDynamicSharedMemorySize, SM_ARG);
    cudaFuncSetAttribute(k_scode_bf16, cudaFuncAttributeMaxDynamicSharedMemorySize, SM_SC);

    k_init<<<256, 256>>>(pcf, plm);
    k_rownorm<<<4096, 256>>>(emb, KS*MN, 0, 0);
    k_rownorm<<<512, 256>>>(pcf, BN, 3, 0);
    k_rownorm<<<512, 256>>>(plm, BN, 3, BN);

    // cmcm scores on original inputs (g_res pre-update) vs last-stage E
    k_scorestc<<<dim3(64, 32, 2), 256>>>(emb);

    for (int s = 0; s < KS; s++) {
        k_argmin<<<dim3(64, 32, 2), 256, SM_ARG>>>(emb, s);
        k_update<<<1024, 256>>>(emb, s);
    }

    k_softmax<<<dim3(BN, 2), 256>>>();
    k_scode_bf16<<<1024, 256, SM_SC>>>();
    k_rowratio<<<BN, 256>>>();

    k_quant<<<QN/256, 256>>>(pcf, plm, out);
    k_ids<<<(2*BN*KS)/256, 256>>>(out);
    k_mse<<<256, 256>>>(pcf, plm, out);
    k_perp<<<8, 256>>>(out);
    k_final<<<1, 256>>>(out);
}